// round 15
// baseline (speedup 1.0000x reference)
#include <cuda_runtime.h>
#include <cuda_fp16.h>
#include <cstdint>
#include <math.h>

#define D      1024
#define DF     4096
#define NTOK   257
#define BSZ    64
#define LAYERS 8
#define HEADS  8
#define HD     128
#define MTOK   (BSZ * NTOK)      /* 16448 */
#define BH     (BSZ * HEADS)     /* 512 */
#define KTOT   384               /* vt row width (layout padding) */
#define QK_ROWS 384

// per-layer fp16 weight offsets (elements), all single-term [N, K]
#define W_QKV   0LL
#define W_PROJ  (3072LL * 1024)
#define W_M1    (W_PROJ + 1024LL * 1024)
#define W_M2    (W_M1  + 4096LL * 1024)
#define W_LAYER (W_M2  + 1024LL * 4096)   /* 12582912 */

// ---------------- scratch (device globals; zero-initialized) ----------------
__device__ float g_t  [MTOK * D];
__device__ __align__(16) __half g_a2 [(size_t)MTOK * D];
__device__ __align__(16) __half g_h  [(size_t)MTOK * DF];
__device__ __align__(16) __half g_q  [(size_t)BH * QK_ROWS * HD];
__device__ __align__(16) __half g_k  [(size_t)BH * QK_ROWS * HD];
__device__ __align__(16) __half g_vt [(size_t)BH * HD * KTOT];
__device__ __align__(16) __half g_wbf[(size_t)LAYERS * W_LAYER];

// ============================ PTX helpers ====================================
__device__ __forceinline__ uint32_t smem_u32(const void* p) {
    uint32_t a;
    asm("{ .reg .u64 t; cvta.to.shared.u64 t, %1; cvt.u32.u64 %0, t; }"
        : "=r"(a) : "l"(p));
    return a;
}
__device__ __forceinline__ void cpasync16(uint32_t s, const void* g, uint32_t sz) {
    asm volatile("cp.async.cg.shared.global [%0], [%1], 16, %2;"
                 :: "r"(s), "l"(g), "r"(sz) : "memory");
}
__device__ __forceinline__ void ldsm4(uint32_t& r0, uint32_t& r1,
                                      uint32_t& r2, uint32_t& r3, uint32_t a) {
    asm volatile("ldmatrix.sync.aligned.m8n8.x4.shared.b16 {%0,%1,%2,%3}, [%4];"
                 : "=r"(r0), "=r"(r1), "=r"(r2), "=r"(r3) : "r"(a));
}
__device__ __forceinline__ void mma16816(float* d, const uint32_t* a,
                                         const uint32_t* b) {
    asm volatile("mma.sync.aligned.m16n8k16.row.col.f32.f16.f16.f32 "
                 "{%0,%1,%2,%3}, {%4,%5,%6,%7}, {%8,%9}, {%0,%1,%2,%3};"
                 : "+f"(d[0]), "+f"(d[1]), "+f"(d[2]), "+f"(d[3])
                 : "r"(a[0]), "r"(a[1]), "r"(a[2]), "r"(a[3]),
                   "r"(b[0]), "r"(b[1]));
}

// ====================== fp16 GEMM ============================================
// C[M,N] = A[M,K](fp16) @ B[N,K]^T(fp16)
// A row m at A + m*lda (elements); C/Res row m at +m*ldc (elements).
// EPI: 2 fp32 C = acc + bias + Res
//      4 fp16 Cs = gelu(acc + bias)
//      6 qkv routing: per-head q/k fp16 + transposed v (smem-staged, coalesced)
#define STG_BYTES 32768
#define GEMM_SMEM (3 * STG_BYTES)

template <int EPI>
__global__ void __launch_bounds__(256, 2)
gemm_mma(const __half* __restrict__ A, const __half* __restrict__ Bw,
         const float* __restrict__ bias, const float* __restrict__ Res,
         float* __restrict__ C, __half* __restrict__ Cs,
         __half* __restrict__ Qh, __half* __restrict__ Kh, __half* __restrict__ Vh,
         int M, int K, int ldc, int lda)
{
    extern __shared__ char smem[];
    const uint32_t sb = smem_u32(smem);
    const int tid  = threadIdx.x;
    const int wid  = tid >> 5, lane = tid & 31;
    const int wm   = wid & 1, wn = wid >> 1;       // 2 x 4 warp grid
    const int row0 = blockIdx.y * 128, col0 = blockIdx.x * 128;

    const long long rowByA = 2LL * lda;
    const long long rowByB = 2LL * K;

    const int ldrow = tid >> 3, ldch = tid & 7;
    const char* gA = (const char*)A  + (long long)(row0 + ldrow) * rowByA + ldch * 16;
    const char* gB = (const char*)Bw + (long long)(col0 + ldrow) * rowByB + ldch * 16;

    auto load_stage = [&](int kt) {
        const uint32_t st = sb + (kt % 3) * STG_BYTES;
        const long long off = (long long)kt * 128;
#pragma unroll
        for (int i = 0; i < 4; i++) {
            int r = i * 32 + ldrow;
            uint32_t so = (uint32_t)(r * 128 + ((ldch ^ (r & 7)) * 16));
            uint32_t szA = (row0 + r < M) ? 16u : 0u;
            const char* a = szA ? (gA + (long long)i * 32 * rowByA + off)
                                : (const char*)A;
            cpasync16(st + so, a, szA);
            cpasync16(st + 16384 + so, gB + (long long)i * 32 * rowByB + off, 16u);
        }
        asm volatile("cp.async.commit_group;" ::: "memory");
    };

    const int grp = lane >> 3, l8 = lane & 7;
    const int aRowB = wm * 64 + (grp & 1) * 8 + l8;
    const int aCG   = grp >> 1;
    const int bRowB = wn * 32 + (grp >> 1) * 8 + l8;
    const int bCG   = grp & 1;

    float acc[4][4][4];
#pragma unroll
    for (int i = 0; i < 4; i++)
#pragma unroll
        for (int j = 0; j < 4; j++)
#pragma unroll
            for (int r = 0; r < 4; r++) acc[i][j][r] = 0.f;

    const int nkt = K / 64;
    load_stage(0);
    load_stage(1);

    for (int kt = 0; kt < nkt; kt++) {
        asm volatile("cp.async.wait_group 1;" ::: "memory");
        __syncthreads();
        if (kt + 2 < nkt) load_stage(kt + 2);
        else asm volatile("cp.async.commit_group;" ::: "memory");

        const uint32_t sA = sb + (kt % 3) * STG_BYTES;
        const uint32_t sB = sA + 16384;

#pragma unroll
        for (int ks = 0; ks < 4; ks++) {
            uint32_t af[4][4], bf2[2][4];
            const uint32_t aSw = (uint32_t)(((ks * 2 + aCG) ^ l8) * 16);
            const uint32_t bSw = (uint32_t)(((ks * 2 + bCG) ^ l8) * 16);
#pragma unroll
            for (int mi = 0; mi < 4; mi++)
                ldsm4(af[mi][0], af[mi][1], af[mi][2], af[mi][3],
                      sA + (uint32_t)((aRowB + mi * 16) * 128) + aSw);
#pragma unroll
            for (int ni2 = 0; ni2 < 2; ni2++)
                ldsm4(bf2[ni2][0], bf2[ni2][1], bf2[ni2][2], bf2[ni2][3],
                      sB + (uint32_t)((bRowB + ni2 * 16) * 128) + bSw);
#pragma unroll
            for (int mi = 0; mi < 4; mi++)
#pragma unroll
                for (int ni = 0; ni < 4; ni++)
                    mma16816(acc[mi][ni], af[mi], &bf2[ni >> 1][(ni & 1) * 2]);
        }
    }

    const bool isv = (EPI == 6) && (col0 >= 2048);
    __half* stile = (__half*)smem;

    // All warps must retire their final ldsm reads of the pipeline stages
    // before any warp overwrites stage 0 with the v staging tile.
    if (isv) __syncthreads();

    // ---- epilogue ----
#pragma unroll
    for (int mi = 0; mi < 4; mi++) {
#pragma unroll
        for (int ni = 0; ni < 4; ni++) {
            float* c = acc[mi][ni];
            int m0 = row0 + wm * 64 + mi * 16 + (lane >> 2);
            int n  = col0 + wn * 32 + ni * 8 + (lane & 3) * 2;
            float b0 = 0.f, b1 = 0.f;
            if (EPI == 2 || EPI == 4) { b0 = bias[n]; b1 = bias[n + 1]; }
#pragma unroll
            for (int half = 0; half < 2; half++) {
                int m = m0 + half * 8;
                if (m >= M && !isv) continue;
                float v0 = c[half * 2 + 0], v1 = c[half * 2 + 1];
                if (EPI == 2) {
                    const float* rp = Res + (size_t)m * ldc + n;
                    v0 += b0 + rp[0]; v1 += b1 + rp[1];
                    *(float2*)(C + (size_t)m * ldc + n) = make_float2(v0, v1);
                }
                if (EPI == 4) {
                    v0 += b0; v1 += b1;
                    v0 = 0.5f * v0 * (1.f + erff(v0 * 0.7071067811865475f));
                    v1 = 0.5f * v1 * (1.f + erff(v1 * 0.7071067811865475f));
                    *(__half2*)(Cs + (size_t)m * ldc + n) = __floats2half2_rn(v0, v1);
                }
                if (EPI == 6) {
                    if (!isv) {
                        int sec = n >> 10, h = (n & 1023) >> 7, hd = n & 127;
                        int b   = m / NTOK, tok = m - b * NTOK;
                        long long bh = (long long)(b * HEADS + h);
                        __half2 hv = __floats2half2_rn(v0, v1);
                        if (sec == 0)
                            *(__half2*)(Qh + (bh * QK_ROWS + tok) * HD + hd) = hv;
                        else
                            *(__half2*)(Kh + (bh * QK_ROWS + tok) * HD + hd) = hv;
                    } else {
                        // stage to smem tile, swizzled: elem (r, c)
                        int r = wm * 64 + mi * 16 + (lane >> 2) + half * 8;
                        int cc = wn * 32 + ni * 8 + (lane & 3) * 2;
                        uint32_t off = (uint32_t)(r * 128
                                     + ((((cc >> 3) ^ (r & 7)) << 3) + (cc & 7)));
                        *(__half2*)(stile + off) = __floats2half2_rn(v0, v1);
                    }
                }
            }
        }
    }

    if (isv) {
        __syncthreads();
        const int h2 = (col0 - 2048) >> 7;        // head (tile spans one head)
#pragma unroll
        for (int nn = 0; nn < 16; nn++) {
            int n = wid * 16 + nn;                 // hd within head
#pragma unroll
            for (int j = 0; j < 4; j++) {
                int mloc = j * 32 + lane;
                int m = row0 + mloc;
                if (m >= M) continue;
                int bb = m / NTOK, tok = m - bb * NTOK;
                uint32_t off = (uint32_t)(mloc * 128
                             + ((((n >> 3) ^ (mloc & 7)) << 3) + (n & 7)));
                Vh[((long long)(bb * HEADS + h2) * HD + n) * KTOT + tok] = stile[off];
            }
        }
    }
}

// ====================== fused flash attention ================================
// grid (mtiles, BH). Covers q rows [0, mtiles*128); keys 0..255 via 2 HMMA
// tiles + key 256 via rank-1 online-softmax update.
#define FA_SQ   0
#define FA_SK   32768
#define FA_SV   98304
#define FA_SP   163840
#define FA_WMAX 196608
#define FA_WSUM 198656
#define FA_XK   200704    /* key 256: 128 half */
#define FA_XV   200960    /* value 256: 128 half */
#define FA_SX   201216    /* s_x per row: 128 float */
#define FA_SMEM 201728

__global__ void __launch_bounds__(256, 1)
flash_attn_k(const __half* __restrict__ Q, const __half* __restrict__ Kb,
             const __half* __restrict__ Vt, __half* __restrict__ Y)
{
    extern __shared__ char smem[];
    const uint32_t sb = smem_u32(smem);
    const int tid = threadIdx.x, wid = tid >> 5, lane = tid & 31;
    const int wm = wid & 1, wn = wid >> 1;
    const int mtile = blockIdx.x;
    const int bh = blockIdx.y;
    const int b = bh >> 3, h = bh & 7;

    const int ldrow = tid >> 3, ldch = tid & 7;
    const char* gQ = (const char*)(Q  + ((size_t)bh * QK_ROWS + mtile * 128) * HD);
    const char* gK = (const char*)(Kb + (size_t)bh * QK_ROWS * HD);
    const char* gV = (const char*)(Vt + (size_t)bh * HD * KTOT);

    auto load_tile = [&](uint32_t dst, const char* src, int rowBytes) {
#pragma unroll
        for (int c = 0; c < 2; c++)
#pragma unroll
            for (int i = 0; i < 4; i++) {
                int r = i * 32 + ldrow;
                uint32_t so = dst + (uint32_t)(c * 16384 + r * 128 + ((ldch ^ (r & 7)) * 16));
                cpasync16(so, src + (long long)r * rowBytes + c * 128 + ldch * 16, 16u);
            }
    };

    load_tile(sb + FA_SQ, gQ, 256);
    load_tile(sb + FA_SK, gK, 256);
    load_tile(sb + FA_SV, gV, 2 * KTOT);
    asm volatile("cp.async.commit_group;" ::: "memory");
    load_tile(sb + FA_SK + 32768, gK + 128 * 256, 256);
    load_tile(sb + FA_SV + 32768, gV + 128 * 2, 2 * KTOT);
    asm volatile("cp.async.commit_group;" ::: "memory");

    // key/value 256 -> smem (plain loads; visible after the kt-loop barriers)
    if (tid < 128)
        ((__half*)(smem + FA_XK))[tid] =
            Kb[((size_t)bh * QK_ROWS + 256) * HD + tid];
    else
        ((__half*)(smem + FA_XV))[tid - 128] =
            Vt[((size_t)bh * HD + (tid - 128)) * KTOT + 256];

    const int grp = lane >> 3, l8 = lane & 7;
    const int aRowB = wm * 64 + (grp & 1) * 8 + l8;
    const int aCG   = grp >> 1;
    const int bRowB = wn * 32 + (grp >> 1) * 8 + l8;
    const int bCG   = grp & 1;
    const int l8r = lane >> 2, qq = lane & 3;

    float* wmax = (float*)(smem + FA_WMAX);   // [4][128]
    float* wsum = (float*)(smem + FA_WSUM);   // [4][128]

    float accO[4][4][4];
#pragma unroll
    for (int i = 0; i < 4; i++)
#pragma unroll
        for (int j = 0; j < 4; j++)
#pragma unroll
            for (int r = 0; r < 4; r++) accO[i][j][r] = 0.f;
    float m_run[8], l_run[8];
#pragma unroll
    for (int i = 0; i < 8; i++) { m_run[i] = -1e30f; l_run[i] = 0.f; }

    auto gemm_tile = [&](uint32_t aBase, uint32_t bBase, float (&acc)[4][4][4]) {
#pragma unroll
        for (int c = 0; c < 2; c++) {
            const uint32_t sA = aBase + c * 16384, sB = bBase + c * 16384;
#pragma unroll
            for (int ks = 0; ks < 4; ks++) {
                uint32_t af[4][4], bf2[2][4];
                const uint32_t aSw = (uint32_t)(((ks * 2 + aCG) ^ l8) * 16);
                const uint32_t bSw = (uint32_t)(((ks * 2 + bCG) ^ l8) * 16);
#pragma unroll
                for (int mi = 0; mi < 4; mi++)
                    ldsm4(af[mi][0], af[mi][1], af[mi][2], af[mi][3],
                          sA + (uint32_t)((aRowB + mi * 16) * 128) + aSw);
#pragma unroll
                for (int ni2 = 0; ni2 < 2; ni2++)
                    ldsm4(bf2[ni2][0], bf2[ni2][1], bf2[ni2][2], bf2[ni2][3],
                          sB + (uint32_t)((bRowB + ni2 * 16) * 128) + bSw);
#pragma unroll
                for (int mi = 0; mi < 4; mi++)
#pragma unroll
                    for (int ni = 0; ni < 4; ni++)
                        mma16816(acc[mi][ni], af[mi], &bf2[ni >> 1][(ni & 1) * 2]);
            }
        }
    };

    for (int kt = 0; kt < 2; kt++) {
        if (kt == 0) asm volatile("cp.async.wait_group 1;" ::: "memory");
        else         asm volatile("cp.async.wait_group 0;" ::: "memory");
        __syncthreads();

        float accS[4][4][4];
#pragma unroll
        for (int i = 0; i < 4; i++)
#pragma unroll
            for (int j = 0; j < 4; j++)
#pragma unroll
                for (int r = 0; r < 4; r++) accS[i][j][r] = 0.f;
        gemm_tile(sb + FA_SQ, sb + FA_SK + kt * 32768, accS);

#pragma unroll
        for (int mi = 0; mi < 4; mi++)
#pragma unroll
            for (int hf = 0; hf < 2; hf++) {
                float r = -1e30f;
#pragma unroll
                for (int ni = 0; ni < 4; ni++) {
                    r = fmaxf(r, accS[mi][ni][hf * 2]);
                    r = fmaxf(r, accS[mi][ni][hf * 2 + 1]);
                }
                r = fmaxf(r, __shfl_xor_sync(0xffffffffu, r, 1));
                r = fmaxf(r, __shfl_xor_sync(0xffffffffu, r, 2));
                if (qq == 0)
                    wmax[wn * 128 + wm * 64 + mi * 16 + hf * 8 + l8r] = r;
            }
        __syncthreads();

        float fscale[8];
#pragma unroll
        for (int mi = 0; mi < 4; mi++)
#pragma unroll
            for (int hf = 0; hf < 2; hf++) {
                int row = wm * 64 + mi * 16 + hf * 8 + l8r;
                float tm = fmaxf(fmaxf(wmax[row], wmax[128 + row]),
                                 fmaxf(wmax[256 + row], wmax[384 + row]));
                int idx = mi * 2 + hf;
                float mnew = fmaxf(m_run[idx], tm);
                float f = __expf(m_run[idx] - mnew);
                m_run[idx] = mnew;
                fscale[idx] = f;
#pragma unroll
                for (int ni = 0; ni < 4; ni++) {
                    accO[mi][ni][hf * 2]     *= f;
                    accO[mi][ni][hf * 2 + 1] *= f;
                }
            }
#pragma unroll
        for (int mi = 0; mi < 4; mi++)
#pragma unroll
            for (int hf = 0; hf < 2; hf++) {
                int idx = mi * 2 + hf;
                int row = wm * 64 + mi * 16 + hf * 8 + l8r;
                float rs = 0.f;
#pragma unroll
                for (int ni = 0; ni < 4; ni++) {
                    int col = wn * 32 + ni * 8 + qq * 2;
                    float p0 = __expf(accS[mi][ni][hf * 2]     - m_run[idx]);
                    float p1 = __expf(accS[mi][ni][hf * 2 + 1] - m_run[idx]);
                    rs += p0 + p1;
                    uint32_t off = (uint32_t)(FA_SP + (col >> 6) * 16384 + row * 128
                                   + ((((col & 63) >> 3) ^ (row & 7)) * 16)
                                   + (col & 7) * 2);
                    *(__half2*)(smem + off) = __floats2half2_rn(p0, p1);
                }
                rs += __shfl_xor_sync(0xffffffffu, rs, 1);
                rs += __shfl_xor_sync(0xffffffffu, rs, 2);
                if (qq == 0) wsum[wn * 128 + row] = rs;
            }
        __syncthreads();
#pragma unroll
        for (int mi = 0; mi < 4; mi++)
#pragma unroll
            for (int hf = 0; hf < 2; hf++) {
                int idx = mi * 2 + hf;
                int row = wm * 64 + mi * 16 + hf * 8 + l8r;
                float rs = wsum[row] + wsum[128 + row] + wsum[256 + row] + wsum[384 + row];
                l_run[idx] = l_run[idx] * fscale[idx] + rs;
            }

        gemm_tile(sb + FA_SP, sb + FA_SV + kt * 32768, accO);
        __syncthreads();
    }

    // ---- extra key 256: s_x = q_row . k256 (2 threads per row) ----
    {
        int row = tid >> 1, hc = tid & 1;
        const __half* xk = (const __half*)(smem + FA_XK);
        float s = 0.f;
#pragma unroll
        for (int cc = 0; cc < 64; cc += 2) {
            int col = hc * 64 + cc;
            uint32_t off = (uint32_t)(FA_SQ + hc * 16384 + row * 128
                         + (((cc >> 3) ^ (row & 7)) << 4) + (cc & 7) * 2);
            float2 qf = __half22float2(*(__half2*)(smem + off));
            float2 kf = __half22float2(*(const __half2*)(xk + col));
            s += qf.x * kf.x + qf.y * kf.y;
        }
        s += __shfl_xor_sync(0xffffffffu, s, 1);
        if (hc == 0) ((float*)(smem + FA_SX))[row] = s;
    }
    __syncthreads();

    // ---- fold key 256 into online softmax + rank-1 O update ----
    {
        const __half* xv = (const __half*)(smem + FA_XV);
        const float* sx = (const float*)(smem + FA_SX);
#pragma unroll
        for (int mi = 0; mi < 4; mi++)
#pragma unroll
            for (int hf = 0; hf < 2; hf++) {
                int idx = mi * 2 + hf;
                int row = wm * 64 + mi * 16 + hf * 8 + l8r;
                float sxr = sx[row];
                float mnew = fmaxf(m_run[idx], sxr);
                float f = __expf(m_run[idx] - mnew);
                float p = __expf(sxr - mnew);
                m_run[idx] = mnew;
                l_run[idx] = l_run[idx] * f + p;
#pragma unroll
                for (int ni = 0; ni < 4; ni++) {
                    int n = wn * 32 + ni * 8 + qq * 2;
                    accO[mi][ni][hf * 2]     = accO[mi][ni][hf * 2] * f
                                             + p * __half2float(xv[n]);
                    accO[mi][ni][hf * 2 + 1] = accO[mi][ni][hf * 2 + 1] * f
                                             + p * __half2float(xv[n + 1]);
                }
            }
    }

    // ---- write out (all rows valid: tok = mtile*128 + row <= 255) ----
#pragma unroll
    for (int mi = 0; mi < 4; mi++)
#pragma unroll
        for (int hf = 0; hf < 2; hf++) {
            int idx = mi * 2 + hf;
            int row = wm * 64 + mi * 16 + hf * 8 + l8r;
            int tok = mtile * 128 + row;
            float inv = 1.f / l_run[idx];
#pragma unroll
            for (int ni = 0; ni < 4; ni++) {
                int n = wn * 32 + ni * 8 + qq * 2;
                float o0 = accO[mi][ni][hf * 2] * inv;
                float o1 = accO[mi][ni][hf * 2 + 1] * inv;
                *(__half2*)(Y + ((size_t)(b * NTOK + tok)) * D + h * HD + n)
                    = __floats2half2_rn(o0, o1);
            }
        }
}

// ====================== attention for query row 256 ==========================
// one CTA per (b,h); exact softmax over all 257 keys.
#define AR_KS   0          /* [257][130] half, padded rows        */
#define AR_Q    66848      /* 128 float                           */
#define AR_SC   67360      /* 257 float scores/probs              */
#define AR_RED  68416      /* 256 float reduce                    */
#define AR_SMEM 69440

__global__ void __launch_bounds__(256)
attn_row_k(const __half* __restrict__ Q, const __half* __restrict__ Kb,
           const __half* __restrict__ Vt, __half* __restrict__ Y)
{
    extern __shared__ char smem[];
    __half* ks  = (__half*)(smem + AR_KS);
    float*  qs  = (float*)(smem + AR_Q);
    float*  sc  = (float*)(smem + AR_SC);
    float*  red = (float*)(smem + AR_RED);
    const int tid = threadIdx.x, bh = blockIdx.x;
    const int b = bh >> 3, h = bh & 7;

    const __half* kbase = Kb + (size_t)bh * QK_ROWS * HD;
    for (int i = tid; i < NTOK * HD; i += 256) {
        int j = i >> 7, d = i & 127;
        ks[j * 130 + d] = kbase[i];
    }
    if (tid < 128)
        qs[tid] = __half2float(Q[((size_t)bh * QK_ROWS + 256) * HD + tid]);
    __syncthreads();

    for (int j = tid; j < NTOK; j += 256) {
        float s = 0.f;
        const __half* kr = ks + j * 130;
#pragma unroll 8
        for (int d = 0; d < 128; d++) s += qs[d] * __half2float(kr[d]);
        sc[j] = s;
    }
    __syncthreads();

    float m = -1e30f;
    for (int j = tid; j < NTOK; j += 256) m = fmaxf(m, sc[j]);
    red[tid] = m; __syncthreads();
    for (int o = 128; o > 0; o >>= 1) {
        if (tid < o) red[tid] = fmaxf(red[tid], red[tid + o]);
        __syncthreads();
    }
    m = red[0]; __syncthreads();

    float s = 0.f;
    for (int j = tid; j < NTOK; j += 256) {
        float p = __expf(sc[j] - m);
        sc[j] = p; s += p;
    }
    red[tid] = s; __syncthreads();
    for (int o = 128; o > 0; o >>= 1) {
        if (tid < o) red[tid] += red[tid + o];
        __syncthreads();
    }
    const float inv = 1.f / red[0];
    __syncthreads();

    if (tid < 128) {
        const __half* vr = Vt + ((size_t)bh * HD + tid) * KTOT;
        float o = 0.f;
        for (int j = 0; j < NTOK; j++) o += sc[j] * __half2float(vr[j]);
        Y[((size_t)(b * NTOK + 256)) * D + h * HD + tid] = __float2half_rn(o * inv);
    }
}

// ====================== conversions ==========================================
// W [K,N] fp32 -> Wt fp16 [N, K] single-term, scaled; z batches layers
__global__ void __launch_bounds__(256)
cvtW1_k(const float* __restrict__ W, __half* __restrict__ Wt,
        int K, int N, float scale, long long srcStride)
{
    W  += (long long)blockIdx.z * srcStride;
    Wt += (long long)blockIdx.z * W_LAYER;
    __shared__ float t[32][33];
    const int n0 = blockIdx.x * 32, k0 = blockIdx.y * 32;
    const int tx = threadIdx.x & 31, ty = threadIdx.x >> 5;
#pragma unroll
    for (int i = 0; i < 4; i++)
        t[ty + i * 8][tx] = W[(size_t)(k0 + ty + i * 8) * N + n0 + tx] * scale;
    __syncthreads();
#pragma unroll
    for (int i = 0; i < 4; i++) {
        int n = n0 + ty + i * 8, k = k0 + tx;
        Wt[(size_t)n * K + k] = __float2half_rn(t[tx][ty + i * 8]);
    }
}

// LayerNorm -> fp16. X row = blockIdx.x * xstride (elements); Y row compact.
__global__ void __launch_bounds__(256)
ln_half_k(const float* __restrict__ X, const float* __restrict__ g,
          const float* __restrict__ b, __half* __restrict__ Y, long long xstride)
{
    const long long row = blockIdx.x;
    const float* x = X + row * xstride;
    const int tid = threadIdx.x;
    float v[4];
    float s = 0.f;
#pragma unroll
    for (int i = 0; i < 4; i++) { v[i] = x[tid + i * 256]; s += v[i]; }

    __shared__ float red[256];
    red[tid] = s; __syncthreads();
    for (int o = 128; o > 0; o >>= 1) {
        if (tid < o) red[tid] += red[tid + o];
        __syncthreads();
    }
    const float mean = red[0] * (1.f / D);
    __syncthreads();
    float sq = 0.f;
#pragma unroll
    for (int i = 0; i < 4; i++) { float d0 = v[i] - mean; sq += d0 * d0; }
    red[tid] = sq; __syncthreads();
    for (int o = 128; o > 0; o >>= 1) {
        if (tid < o) red[tid] += red[tid + o];
        __syncthreads();
    }
    const float rstd = rsqrtf(red[0] * (1.f / D) + 1e-6f);

    __half* y = Y + row * D;
#pragma unroll
    for (int i = 0; i < 4; i++) {
        int d0 = tid + i * 256;
        y[d0] = __float2half_rn((v[i] - mean) * rstd * g[d0] + b[d0]);
    }
}

// ====================== embed / out ==========================================
__global__ void __launch_bounds__(256)
patch_k(const float* __restrict__ x, const float* __restrict__ w,
        const float* __restrict__ cb, const float* __restrict__ pe,
        float* __restrict__ T)
{
    const int p  = blockIdx.x;
    const int b  = p >> 8, pp = p & 255;
    const int py = pp >> 4, px = pp & 15;
    const int tid = threadIdx.x;

    __shared__ float patch[48];
    if (tid < 48) {
        int ky = tid / 12, kx = (tid % 12) / 3, cc = tid % 3;
        patch[tid] = x[(((b * 64) + py * 4 + ky) * 64 + (px * 4 + kx)) * 3 + cc];
    }
    __syncthreads();

    float acc[4];
#pragma unroll
    for (int i = 0; i < 4; i++) acc[i] = cb[tid + i * 256];
#pragma unroll
    for (int k = 0; k < 48; k++) {
        float pk = patch[k];
#pragma unroll
        for (int i = 0; i < 4; i++)
            acc[i] = fmaf(pk, w[k * D + tid + i * 256], acc[i]);
    }
    long long base = ((long long)(b * NTOK + 1 + pp)) * D;
#pragma unroll
    for (int i = 0; i < 4; i++) {
        int d0 = tid + i * 256;
        T[base + d0] = acc[i] + pe[(long long)(1 + pp) * D + d0];
    }
}

__global__ void __launch_bounds__(256)
cls_k(const float* __restrict__ cls, const float* __restrict__ pe,
      float* __restrict__ T)
{
    const int b = blockIdx.x, tid = threadIdx.x;
#pragma unroll
    for (int i = 0; i < 4; i++) {
        int d0 = tid + i * 256;
        T[(long long)b * NTOK * D + d0] = cls[d0] + pe[d0];
    }
}

__global__ void __launch_bounds__(256)
out_k(const float* __restrict__ T, float* __restrict__ out)
{
    const int b = blockIdx.x, tid = threadIdx.x;
#pragma unroll
    for (int i = 0; i < 4; i++) {
        int d0 = tid + i * 256;
        out[(long long)b * D + d0] = T[(long long)b * NTOK * D + d0];
    }
}

// ====================== orchestration ========================================
extern "C" void kernel_launch(void* const* d_in, const int* in_sizes, int n_in,
                              void* d_out, int out_size)
{
    const float* x        = (const float*)d_in[0];
    const float* conv_w   = (const float*)d_in[1];
    const float* conv_b   = (const float*)d_in[2];
    const float* cls_tok  = (const float*)d_in[3];
    const float* pos_emb  = (const float*)d_in[4];
    const float* ln1_g    = (const float*)d_in[5];
    const float* ln1_b    = (const float*)d_in[6];
    const float* wq       = (const float*)d_in[7];
    const float* wk       = (const float*)d_in[8];
    const float* wv       = (const float*)d_in[9];
    const float* proj_w   = (const float*)d_in[10];
    const float* proj_b   = (const float*)d_in[11];
    const float* ln2_g    = (const float*)d_in[12];
    const float* ln2_b    = (const float*)d_in[13];
    const float* mlp1_w   = (const float*)d_in[14];
    const float* mlp1_b   = (const float*)d_in[15];
    const float* mlp2_w   = (const float*)d_in[16];
    const float* mlp2_b   = (const float*)d_in[17];
    float* out = (float*)d_out;

    float *t;
    __half *a2, *hbuf, *qb, *kb, *vt, *wbf;
    cudaGetSymbolAddress((void**)&t,    g_t);
    cudaGetSymbolAddress((void**)&a2,   g_a2);
    cudaGetSymbolAddress((void**)&hbuf, g_h);
    cudaGetSymbolAddress((void**)&qb,   g_q);
    cudaGetSymbolAddress((void**)&kb,   g_k);
    cudaGetSymbolAddress((void**)&vt,   g_vt);
    cudaGetSymbolAddress((void**)&wbf,  g_wbf);

    cudaFuncSetAttribute((void*)gemm_mma<2>, cudaFuncAttributeMaxDynamicSharedMemorySize, GEMM_SMEM);
    cudaFuncSetAttribute((void*)gemm_mma<4>, cudaFuncAttributeMaxDynamicSharedMemorySize, GEMM_SMEM);
    cudaFuncSetAttribute((void*)gemm_mma<6>, cudaFuncAttributeMaxDynamicSharedMemorySize, GEMM_SMEM);
    cudaFuncSetAttribute((void*)flash_attn_k, cudaFuncAttributeMaxDynamicSharedMemorySize, FA_SMEM);
    cudaFuncSetAttribute((void*)attn_row_k, cudaFuncAttributeMaxDynamicSharedMemorySize, AR_SMEM);

    const float qscale = 0.08838834764831845f;   // 128^-0.5
    const int TD = NTOK * D;                      // t row stride per batch cls row

    // ---- weight conversion (batched over layers via gridDim.z) ----
    {
        const long long sDD = (long long)D * D;
        const long long sDF = (long long)D * DF;
        cvtW1_k<<<dim3(D / 32, D / 32, LAYERS), 256>>>(wq, wbf, D, D, qscale, sDD);
        cvtW1_k<<<dim3(D / 32, D / 32, LAYERS), 256>>>(wk, wbf + 1024LL * 1024,
                                                       D, D, 1.f, sDD);
        cvtW1_k<<<dim3(D / 32, D / 32, LAYERS), 256>>>(wv, wbf + 2048LL * 1024,
                                                       D, D, 1.f, sDD);
        cvtW1_k<<<dim3(D / 32, D / 32, LAYERS), 256>>>(proj_w, wbf + W_PROJ,
                                                       D, D, 1.f, sDD);
        cvtW1_k<<<dim3(DF / 32, D / 32, LAYERS), 256>>>(mlp1_w, wbf + W_M1,
                                                        D, DF, 1.f, sDF);
        cvtW1_k<<<dim3(D / 32, DF / 32, LAYERS), 256>>>(mlp2_w, wbf + W_M2,
                                                        DF, D, 1.f, sDF);
    }

    // ---- embed ----
    patch_k<<<BSZ * 256, 256>>>(x, conv_w, conv_b, pos_emb, t);
    cls_k<<<BSZ, 256>>>(cls_tok, pos_emb, t);

    const int Mt = (MTOK + 127) / 128;                 // 129
    const dim3 gQKV(24, Mt);
    const dim3 gD  (8, Mt);
    const dim3 gDF (32, Mt);

    for (int i = 0; i < LAYERS; i++) {
        const __half* wl = wbf + (size_t)i * W_LAYER;
        const float* pb_i = proj_b + (size_t)i * D;
        const float* m1b  = mlp1_b + (size_t)i * DF;
        const float* m2b  = mlp2_b + (size_t)i * D;
        const bool last = (i == LAYERS - 1);

        // LN1 -> fp16 (full; K/V need all tokens)
        ln_half_k<<<MTOK, 256>>>(t, ln1_g + (size_t)i * D, ln1_b + (size_t)i * D,
                                 a2, D);

        // QKV single-term, epilogue routes q/k per-head + v transposed (staged)
        gemm_mma<6><<<gQKV, 256, GEMM_SMEM>>>(a2, wl, nullptr, nullptr,
            nullptr, nullptr, qb, kb, vt, MTOK, D, 0, D);

        // fused attention -> a2; last layer: only cls q-tile
        flash_attn_k<<<last ? dim3(1, BH) : dim3(2, BH), 256, FA_SMEM>>>(qb, kb, vt, a2);
        if (!last)
            attn_row_k<<<BH, 256, AR_SMEM>>>(qb, kb, vt, a2);

        if (!last) {
            // t += y @ proj_w + proj_b
            gemm_mma<2><<<gD, 256, GEMM_SMEM>>>(a2, wl + W_PROJ, pb_i, t, t,
                nullptr, nullptr, nullptr, nullptr, MTOK, D, D, D);

            // LN2 -> fp16
            ln_half_k<<<MTOK, 256>>>(t, ln2_g + (size_t)i * D,
                                     ln2_b + (size_t)i * D, a2, D);

            // h = gelu(xn @ mlp1_w + b) -> fp16
            gemm_mma<4><<<gDF, 256, GEMM_SMEM>>>(a2, wl + W_M1, m1b, nullptr,
                nullptr, hbuf, nullptr, nullptr, nullptr, MTOK, D, DF, D);

            // t += h @ mlp2_w + b
            gemm_mma<2><<<gD, 256, GEMM_SMEM>>>(hbuf, wl + W_M2, m2b, t, t,
                nullptr, nullptr, nullptr, nullptr, MTOK, DF, D, DF);
        } else {
            // --- last layer: only the 64 cls rows matter downstream ---
            gemm_mma<2><<<dim3(8, 1), 256, GEMM_SMEM>>>(a2, wl + W_PROJ, pb_i,
                t, t, nullptr, nullptr, nullptr, nullptr, BSZ, D, TD, TD);

            ln_half_k<<<BSZ, 256>>>(t, ln2_g + (size_t)i * D,
                                    ln2_b + (size_t)i * D, a2, TD);

            gemm_mma<4><<<dim3(32, 1), 256, GEMM_SMEM>>>(a2, wl + W_M1, m1b,
                nullptr, nullptr, hbuf, nullptr, nullptr, nullptr,
                BSZ, D, DF, D);

            gemm_mma<2><<<dim3(8, 1), 256, GEMM_SMEM>>>(hbuf, wl + W_M2, m2b,
                t, t, nullptr, nullptr, nullptr, nullptr, BSZ, DF, TD, DF);
        }
    }

    out_k<<<BSZ, 256>>>(t, out);
}

// round 16
// speedup vs baseline: 1.0487x; 1.0487x over previous
#include <cuda_runtime.h>
#include <cuda_fp16.h>
#include <cstdint>
#include <math.h>

#define D      1024
#define DF     4096
#define NTOK   257
#define BSZ    64
#define LAYERS 8
#define HEADS  8
#define HD     128
#define MTOK   (BSZ * NTOK)      /* 16448 */
#define BH     (BSZ * HEADS)     /* 512 */
#define KTOT   384               /* vt row width (layout padding) */
#define QK_ROWS 384

// per-layer fp16 weight offsets (elements), all single-term [N, K]
#define W_QKV   0LL
#define W_PROJ  (3072LL * 1024)
#define W_M1    (W_PROJ + 1024LL * 1024)
#define W_M2    (W_M1  + 4096LL * 1024)
#define W_LAYER (W_M2  + 1024LL * 4096)   /* 12582912 */

// ---------------- scratch (device globals; zero-initialized) ----------------
__device__ float g_t  [MTOK * D];
__device__ __align__(16) __half g_a2 [(size_t)MTOK * D];
__device__ __align__(16) __half g_h  [(size_t)MTOK * DF];
__device__ __align__(16) __half g_q  [(size_t)BH * QK_ROWS * HD];
__device__ __align__(16) __half g_k  [(size_t)BH * QK_ROWS * HD];
__device__ __align__(16) __half g_vt [(size_t)BH * HD * KTOT];
__device__ __align__(16) __half g_wbf[(size_t)LAYERS * W_LAYER];

// ============================ PTX helpers ====================================
__device__ __forceinline__ uint32_t smem_u32(const void* p) {
    uint32_t a;
    asm("{ .reg .u64 t; cvta.to.shared.u64 t, %1; cvt.u32.u64 %0, t; }"
        : "=r"(a) : "l"(p));
    return a;
}
__device__ __forceinline__ void cpasync16(uint32_t s, const void* g, uint32_t sz) {
    asm volatile("cp.async.cg.shared.global [%0], [%1], 16, %2;"
                 :: "r"(s), "l"(g), "r"(sz) : "memory");
}
__device__ __forceinline__ void ldsm4(uint32_t& r0, uint32_t& r1,
                                      uint32_t& r2, uint32_t& r3, uint32_t a) {
    asm volatile("ldmatrix.sync.aligned.m8n8.x4.shared.b16 {%0,%1,%2,%3}, [%4];"
                 : "=r"(r0), "=r"(r1), "=r"(r2), "=r"(r3) : "r"(a));
}
__device__ __forceinline__ void mma16816(float* d, const uint32_t* a,
                                         const uint32_t* b) {
    asm volatile("mma.sync.aligned.m16n8k16.row.col.f32.f16.f16.f32 "
                 "{%0,%1,%2,%3}, {%4,%5,%6,%7}, {%8,%9}, {%0,%1,%2,%3};"
                 : "+f"(d[0]), "+f"(d[1]), "+f"(d[2]), "+f"(d[3])
                 : "r"(a[0]), "r"(a[1]), "r"(a[2]), "r"(a[3]),
                   "r"(b[0]), "r"(b[1]));
}

// ====================== fp16 GEMM ============================================
// C[M,N] = A[M,K](fp16) @ B[N,K]^T(fp16)
// A row m at A + m*lda (elements); C/Res row m at +m*ldc (elements).
// EPI: 2 fp32 C = acc + bias + Res
//      4 fp16 Cs = gelu(acc + bias)
//      6 qkv routing: per-head q/k fp16 + transposed v (smem-staged, coalesced)
#define STG_BYTES 32768
#define GEMM_SMEM (3 * STG_BYTES)

template <int EPI>
__global__ void __launch_bounds__(256, 2)
gemm_mma(const __half* __restrict__ A, const __half* __restrict__ Bw,
         const float* __restrict__ bias, const float* __restrict__ Res,
         float* __restrict__ C, __half* __restrict__ Cs,
         __half* __restrict__ Qh, __half* __restrict__ Kh, __half* __restrict__ Vh,
         int M, int K, int ldc, int lda)
{
    extern __shared__ char smem[];
    const uint32_t sb = smem_u32(smem);
    const int tid  = threadIdx.x;
    const int wid  = tid >> 5, lane = tid & 31;
    const int wm   = wid & 1, wn = wid >> 1;       // 2 x 4 warp grid
    const int row0 = blockIdx.y * 128, col0 = blockIdx.x * 128;

    const long long rowByA = 2LL * lda;
    const long long rowByB = 2LL * K;

    const int ldrow = tid >> 3, ldch = tid & 7;
    const char* gA = (const char*)A  + (long long)(row0 + ldrow) * rowByA + ldch * 16;
    const char* gB = (const char*)Bw + (long long)(col0 + ldrow) * rowByB + ldch * 16;

    auto load_stage = [&](int kt) {
        const uint32_t st = sb + (kt % 3) * STG_BYTES;
        const long long off = (long long)kt * 128;
#pragma unroll
        for (int i = 0; i < 4; i++) {
            int r = i * 32 + ldrow;
            uint32_t so = (uint32_t)(r * 128 + ((ldch ^ (r & 7)) * 16));
            uint32_t szA = (row0 + r < M) ? 16u : 0u;
            const char* a = szA ? (gA + (long long)i * 32 * rowByA + off)
                                : (const char*)A;
            cpasync16(st + so, a, szA);
            cpasync16(st + 16384 + so, gB + (long long)i * 32 * rowByB + off, 16u);
        }
        asm volatile("cp.async.commit_group;" ::: "memory");
    };

    const int grp = lane >> 3, l8 = lane & 7;
    const int aRowB = wm * 64 + (grp & 1) * 8 + l8;
    const int aCG   = grp >> 1;
    const int bRowB = wn * 32 + (grp >> 1) * 8 + l8;
    const int bCG   = grp & 1;

    float acc[4][4][4];
#pragma unroll
    for (int i = 0; i < 4; i++)
#pragma unroll
        for (int j = 0; j < 4; j++)
#pragma unroll
            for (int r = 0; r < 4; r++) acc[i][j][r] = 0.f;

    const int nkt = K / 64;
    load_stage(0);
    load_stage(1);

    for (int kt = 0; kt < nkt; kt++) {
        asm volatile("cp.async.wait_group 1;" ::: "memory");
        __syncthreads();
        if (kt + 2 < nkt) load_stage(kt + 2);
        else asm volatile("cp.async.commit_group;" ::: "memory");

        const uint32_t sA = sb + (kt % 3) * STG_BYTES;
        const uint32_t sB = sA + 16384;

#pragma unroll
        for (int ks = 0; ks < 4; ks++) {
            uint32_t af[4][4], bf2[2][4];
            const uint32_t aSw = (uint32_t)(((ks * 2 + aCG) ^ l8) * 16);
            const uint32_t bSw = (uint32_t)(((ks * 2 + bCG) ^ l8) * 16);
#pragma unroll
            for (int mi = 0; mi < 4; mi++)
                ldsm4(af[mi][0], af[mi][1], af[mi][2], af[mi][3],
                      sA + (uint32_t)((aRowB + mi * 16) * 128) + aSw);
#pragma unroll
            for (int ni2 = 0; ni2 < 2; ni2++)
                ldsm4(bf2[ni2][0], bf2[ni2][1], bf2[ni2][2], bf2[ni2][3],
                      sB + (uint32_t)((bRowB + ni2 * 16) * 128) + bSw);
#pragma unroll
            for (int mi = 0; mi < 4; mi++)
#pragma unroll
                for (int ni = 0; ni < 4; ni++)
                    mma16816(acc[mi][ni], af[mi], &bf2[ni >> 1][(ni & 1) * 2]);
        }
    }

    const bool isv = (EPI == 6) && (col0 >= 2048);
    __half* stile = (__half*)smem;

    // All warps must retire their final ldsm reads of the pipeline stages
    // before any warp overwrites stage 0 with the v staging tile.
    if (isv) __syncthreads();

    // ---- epilogue ----
#pragma unroll
    for (int mi = 0; mi < 4; mi++) {
#pragma unroll
        for (int ni = 0; ni < 4; ni++) {
            float* c = acc[mi][ni];
            int m0 = row0 + wm * 64 + mi * 16 + (lane >> 2);
            int n  = col0 + wn * 32 + ni * 8 + (lane & 3) * 2;
            float b0 = 0.f, b1 = 0.f;
            if (EPI == 2 || EPI == 4) { b0 = bias[n]; b1 = bias[n + 1]; }
#pragma unroll
            for (int half = 0; half < 2; half++) {
                int m = m0 + half * 8;
                if (m >= M && !isv) continue;
                float v0 = c[half * 2 + 0], v1 = c[half * 2 + 1];
                if (EPI == 2) {
                    const float* rp = Res + (size_t)m * ldc + n;
                    v0 += b0 + rp[0]; v1 += b1 + rp[1];
                    *(float2*)(C + (size_t)m * ldc + n) = make_float2(v0, v1);
                }
                if (EPI == 4) {
                    v0 += b0; v1 += b1;
                    v0 = 0.5f * v0 * (1.f + erff(v0 * 0.7071067811865475f));
                    v1 = 0.5f * v1 * (1.f + erff(v1 * 0.7071067811865475f));
                    *(__half2*)(Cs + (size_t)m * ldc + n) = __floats2half2_rn(v0, v1);
                }
                if (EPI == 6) {
                    if (!isv) {
                        int sec = n >> 10, h = (n & 1023) >> 7, hd = n & 127;
                        int b   = m / NTOK, tok = m - b * NTOK;
                        long long bh = (long long)(b * HEADS + h);
                        __half2 hv = __floats2half2_rn(v0, v1);
                        if (sec == 0)
                            *(__half2*)(Qh + (bh * QK_ROWS + tok) * HD + hd) = hv;
                        else
                            *(__half2*)(Kh + (bh * QK_ROWS + tok) * HD + hd) = hv;
                    } else {
                        // stage to smem tile, swizzled: elem (r, c)
                        int r = wm * 64 + mi * 16 + (lane >> 2) + half * 8;
                        int cc = wn * 32 + ni * 8 + (lane & 3) * 2;
                        uint32_t off = (uint32_t)(r * 128
                                     + ((((cc >> 3) ^ (r & 7)) << 3) + (cc & 7)));
                        *(__half2*)(stile + off) = __floats2half2_rn(v0, v1);
                    }
                }
            }
        }
    }

    if (isv) {
        __syncthreads();
        const int h2 = (col0 - 2048) >> 7;        // head (tile spans one head)
#pragma unroll
        for (int nn = 0; nn < 16; nn++) {
            int n = wid * 16 + nn;                 // hd within head
#pragma unroll
            for (int j = 0; j < 4; j++) {
                int mloc = j * 32 + lane;
                int m = row0 + mloc;
                if (m >= M) continue;
                int bb = m / NTOK, tok = m - bb * NTOK;
                uint32_t off = (uint32_t)(mloc * 128
                             + ((((n >> 3) ^ (mloc & 7)) << 3) + (n & 7)));
                Vh[((long long)(bb * HEADS + h2) * HD + n) * KTOT + tok] = stile[off];
            }
        }
    }
}

// ====================== fused flash attention ================================
// grid (mtiles, BH). Keys 0..255 via 2 HMMA K-tiles + key 256 via rank-1
// online-softmax fold (all in-kernel). Q pad rows are zero (harmless).
#define FA_SQ   0
#define FA_SK   32768
#define FA_SV   98304
#define FA_SP   163840
#define FA_WMAX 196608
#define FA_WSUM 198656
#define FA_XK   200704    /* key 256: 128 half */
#define FA_XV   200960    /* value 256: 128 half */
#define FA_SX   201216    /* s_x per row: 128 float */
#define FA_SMEM 201728

__global__ void __launch_bounds__(256, 1)
flash_attn_k(const __half* __restrict__ Q, const __half* __restrict__ Kb,
             const __half* __restrict__ Vt, __half* __restrict__ Y)
{
    extern __shared__ char smem[];
    const uint32_t sb = smem_u32(smem);
    const int tid = threadIdx.x, wid = tid >> 5, lane = tid & 31;
    const int wm = wid & 1, wn = wid >> 1;
    const int mtile = blockIdx.x;
    const int bh = blockIdx.y;
    const int b = bh >> 3, h = bh & 7;

    const int ldrow = tid >> 3, ldch = tid & 7;
    const char* gQ = (const char*)(Q  + ((size_t)bh * QK_ROWS + mtile * 128) * HD);
    const char* gK = (const char*)(Kb + (size_t)bh * QK_ROWS * HD);
    const char* gV = (const char*)(Vt + (size_t)bh * HD * KTOT);

    auto load_tile = [&](uint32_t dst, const char* src, int rowBytes) {
#pragma unroll
        for (int c = 0; c < 2; c++)
#pragma unroll
            for (int i = 0; i < 4; i++) {
                int r = i * 32 + ldrow;
                uint32_t so = dst + (uint32_t)(c * 16384 + r * 128 + ((ldch ^ (r & 7)) * 16));
                cpasync16(so, src + (long long)r * rowBytes + c * 128 + ldch * 16, 16u);
            }
    };

    load_tile(sb + FA_SQ, gQ, 256);
    load_tile(sb + FA_SK, gK, 256);
    load_tile(sb + FA_SV, gV, 2 * KTOT);
    asm volatile("cp.async.commit_group;" ::: "memory");
    load_tile(sb + FA_SK + 32768, gK + 128 * 256, 256);
    load_tile(sb + FA_SV + 32768, gV + 128 * 2, 2 * KTOT);
    asm volatile("cp.async.commit_group;" ::: "memory");

    // key/value 256 -> smem (plain stores; visible after first __syncthreads)
    if (tid < 128)
        ((__half*)(smem + FA_XK))[tid] =
            Kb[((size_t)bh * QK_ROWS + 256) * HD + tid];
    else
        ((__half*)(smem + FA_XV))[tid - 128] =
            Vt[((size_t)bh * HD + (tid - 128)) * KTOT + 256];

    const int grp = lane >> 3, l8 = lane & 7;
    const int aRowB = wm * 64 + (grp & 1) * 8 + l8;
    const int aCG   = grp >> 1;
    const int bRowB = wn * 32 + (grp >> 1) * 8 + l8;
    const int bCG   = grp & 1;
    const int l8r = lane >> 2, qq = lane & 3;

    float* wmax = (float*)(smem + FA_WMAX);   // [4][128]
    float* wsum = (float*)(smem + FA_WSUM);   // [4][128]

    float accO[4][4][4];
#pragma unroll
    for (int i = 0; i < 4; i++)
#pragma unroll
        for (int j = 0; j < 4; j++)
#pragma unroll
            for (int r = 0; r < 4; r++) accO[i][j][r] = 0.f;
    float m_run[8], l_run[8];
#pragma unroll
    for (int i = 0; i < 8; i++) { m_run[i] = -1e30f; l_run[i] = 0.f; }

    auto gemm_tile = [&](uint32_t aBase, uint32_t bBase, float (&acc)[4][4][4]) {
#pragma unroll
        for (int c = 0; c < 2; c++) {
            const uint32_t sA = aBase + c * 16384, sB = bBase + c * 16384;
#pragma unroll
            for (int ks = 0; ks < 4; ks++) {
                uint32_t af[4][4], bf2[2][4];
                const uint32_t aSw = (uint32_t)(((ks * 2 + aCG) ^ l8) * 16);
                const uint32_t bSw = (uint32_t)(((ks * 2 + bCG) ^ l8) * 16);
#pragma unroll
                for (int mi = 0; mi < 4; mi++)
                    ldsm4(af[mi][0], af[mi][1], af[mi][2], af[mi][3],
                          sA + (uint32_t)((aRowB + mi * 16) * 128) + aSw);
#pragma unroll
                for (int ni2 = 0; ni2 < 2; ni2++)
                    ldsm4(bf2[ni2][0], bf2[ni2][1], bf2[ni2][2], bf2[ni2][3],
                          sB + (uint32_t)((bRowB + ni2 * 16) * 128) + bSw);
#pragma unroll
                for (int mi = 0; mi < 4; mi++)
#pragma unroll
                    for (int ni = 0; ni < 4; ni++)
                        mma16816(acc[mi][ni], af[mi], &bf2[ni >> 1][(ni & 1) * 2]);
            }
        }
    };

    for (int kt = 0; kt < 2; kt++) {
        if (kt == 0) asm volatile("cp.async.wait_group 1;" ::: "memory");
        else         asm volatile("cp.async.wait_group 0;" ::: "memory");
        __syncthreads();

        float accS[4][4][4];
#pragma unroll
        for (int i = 0; i < 4; i++)
#pragma unroll
            for (int j = 0; j < 4; j++)
#pragma unroll
                for (int r = 0; r < 4; r++) accS[i][j][r] = 0.f;
        gemm_tile(sb + FA_SQ, sb + FA_SK + kt * 32768, accS);

#pragma unroll
        for (int mi = 0; mi < 4; mi++)
#pragma unroll
            for (int hf = 0; hf < 2; hf++) {
                float r = -1e30f;
#pragma unroll
                for (int ni = 0; ni < 4; ni++) {
                    r = fmaxf(r, accS[mi][ni][hf * 2]);
                    r = fmaxf(r, accS[mi][ni][hf * 2 + 1]);
                }
                r = fmaxf(r, __shfl_xor_sync(0xffffffffu, r, 1));
                r = fmaxf(r, __shfl_xor_sync(0xffffffffu, r, 2));
                if (qq == 0)
                    wmax[wn * 128 + wm * 64 + mi * 16 + hf * 8 + l8r] = r;
            }
        __syncthreads();

        float fscale[8];
#pragma unroll
        for (int mi = 0; mi < 4; mi++)
#pragma unroll
            for (int hf = 0; hf < 2; hf++) {
                int row = wm * 64 + mi * 16 + hf * 8 + l8r;
                float tm = fmaxf(fmaxf(wmax[row], wmax[128 + row]),
                                 fmaxf(wmax[256 + row], wmax[384 + row]));
                int idx = mi * 2 + hf;
                float mnew = fmaxf(m_run[idx], tm);
                float f = __expf(m_run[idx] - mnew);
                m_run[idx] = mnew;
                fscale[idx] = f;
#pragma unroll
                for (int ni = 0; ni < 4; ni++) {
                    accO[mi][ni][hf * 2]     *= f;
                    accO[mi][ni][hf * 2 + 1] *= f;
                }
            }
#pragma unroll
        for (int mi = 0; mi < 4; mi++)
#pragma unroll
            for (int hf = 0; hf < 2; hf++) {
                int idx = mi * 2 + hf;
                int row = wm * 64 + mi * 16 + hf * 8 + l8r;
                float rs = 0.f;
#pragma unroll
                for (int ni = 0; ni < 4; ni++) {
                    int col = wn * 32 + ni * 8 + qq * 2;
                    float p0 = __expf(accS[mi][ni][hf * 2]     - m_run[idx]);
                    float p1 = __expf(accS[mi][ni][hf * 2 + 1] - m_run[idx]);
                    rs += p0 + p1;
                    uint32_t off = (uint32_t)(FA_SP + (col >> 6) * 16384 + row * 128
                                   + ((((col & 63) >> 3) ^ (row & 7)) * 16)
                                   + (col & 7) * 2);
                    *(__half2*)(smem + off) = __floats2half2_rn(p0, p1);
                }
                rs += __shfl_xor_sync(0xffffffffu, rs, 1);
                rs += __shfl_xor_sync(0xffffffffu, rs, 2);
                if (qq == 0) wsum[wn * 128 + row] = rs;
            }
        __syncthreads();
#pragma unroll
        for (int mi = 0; mi < 4; mi++)
#pragma unroll
            for (int hf = 0; hf < 2; hf++) {
                int idx = mi * 2 + hf;
                int row = wm * 64 + mi * 16 + hf * 8 + l8r;
                float rs = wsum[row] + wsum[128 + row] + wsum[256 + row] + wsum[384 + row];
                l_run[idx] = l_run[idx] * fscale[idx] + rs;
            }

        gemm_tile(sb + FA_SP, sb + FA_SV + kt * 32768, accO);
        __syncthreads();
    }

    // ---- extra key 256: s_x = q_row . k256 (2 threads per row) ----
    {
        int row = tid >> 1, hc = tid & 1;
        const __half* xk = (const __half*)(smem + FA_XK);
        float s = 0.f;
#pragma unroll
        for (int cc = 0; cc < 64; cc += 2) {
            int col = hc * 64 + cc;
            uint32_t off = (uint32_t)(FA_SQ + hc * 16384 + row * 128
                         + (((cc >> 3) ^ (row & 7)) << 4) + (cc & 7) * 2);
            float2 qf = __half22float2(*(__half2*)(smem + off));
            float2 kf = __half22float2(*(const __half2*)(xk + col));
            s += qf.x * kf.x + qf.y * kf.y;
        }
        s += __shfl_xor_sync(0xffffffffu, s, 1);
        if (hc == 0) ((float*)(smem + FA_SX))[row] = s;
    }
    __syncthreads();

    // ---- fold key 256 into online softmax + rank-1 O update ----
    {
        const __half* xv = (const __half*)(smem + FA_XV);
        const float* sx = (const float*)(smem + FA_SX);
#pragma unroll
        for (int mi = 0; mi < 4; mi++)
#pragma unroll
            for (int hf = 0; hf < 2; hf++) {
                int idx = mi * 2 + hf;
                int row = wm * 64 + mi * 16 + hf * 8 + l8r;
                float sxr = sx[row];
                float mnew = fmaxf(m_run[idx], sxr);
                float f = __expf(m_run[idx] - mnew);
                float p = __expf(sxr - mnew);
                m_run[idx] = mnew;
                l_run[idx] = l_run[idx] * f + p;
#pragma unroll
                for (int ni = 0; ni < 4; ni++) {
                    int n = wn * 32 + ni * 8 + qq * 2;
                    accO[mi][ni][hf * 2]     = accO[mi][ni][hf * 2] * f
                                             + p * __half2float(xv[n]);
                    accO[mi][ni][hf * 2 + 1] = accO[mi][ni][hf * 2 + 1] * f
                                             + p * __half2float(xv[n + 1]);
                }
            }
    }

    // ---- write out ----
#pragma unroll
    for (int mi = 0; mi < 4; mi++)
#pragma unroll
        for (int hf = 0; hf < 2; hf++) {
            int idx = mi * 2 + hf;
            int row = wm * 64 + mi * 16 + hf * 8 + l8r;
            int tok = mtile * 128 + row;
            if (tok >= NTOK) continue;
            float inv = 1.f / l_run[idx];
#pragma unroll
            for (int ni = 0; ni < 4; ni++) {
                int n = wn * 32 + ni * 8 + qq * 2;
                float o0 = accO[mi][ni][hf * 2] * inv;
                float o1 = accO[mi][ni][hf * 2 + 1] * inv;
                *(__half2*)(Y + ((size_t)(b * NTOK + tok)) * D + h * HD + n)
                    = __floats2half2_rn(o0, o1);
            }
        }
}

// ====================== conversions ==========================================
// W [K,N] fp32 -> Wt fp16 [N, K] single-term, scaled; z batches layers
__global__ void __launch_bounds__(256)
cvtW1_k(const float* __restrict__ W, __half* __restrict__ Wt,
        int K, int N, float scale, long long srcStride)
{
    W  += (long long)blockIdx.z * srcStride;
    Wt += (long long)blockIdx.z * W_LAYER;
    __shared__ float t[32][33];
    const int n0 = blockIdx.x * 32, k0 = blockIdx.y * 32;
    const int tx = threadIdx.x & 31, ty = threadIdx.x >> 5;
#pragma unroll
    for (int i = 0; i < 4; i++)
        t[ty + i * 8][tx] = W[(size_t)(k0 + ty + i * 8) * N + n0 + tx] * scale;
    __syncthreads();
#pragma unroll
    for (int i = 0; i < 4; i++) {
        int n = n0 + ty + i * 8, k = k0 + tx;
        Wt[(size_t)n * K + k] = __float2half_rn(t[tx][ty + i * 8]);
    }
}

// LayerNorm -> fp16. X row = blockIdx.x * xstride (elements); Y row compact.
__global__ void __launch_bounds__(256)
ln_half_k(const float* __restrict__ X, const float* __restrict__ g,
          const float* __restrict__ b, __half* __restrict__ Y, long long xstride)
{
    const long long row = blockIdx.x;
    const float* x = X + row * xstride;
    const int tid = threadIdx.x;
    float v[4];
    float s = 0.f;
#pragma unroll
    for (int i = 0; i < 4; i++) { v[i] = x[tid + i * 256]; s += v[i]; }

    __shared__ float red[256];
    red[tid] = s; __syncthreads();
    for (int o = 128; o > 0; o >>= 1) {
        if (tid < o) red[tid] += red[tid + o];
        __syncthreads();
    }
    const float mean = red[0] * (1.f / D);
    __syncthreads();
    float sq = 0.f;
#pragma unroll
    for (int i = 0; i < 4; i++) { float d0 = v[i] - mean; sq += d0 * d0; }
    red[tid] = sq; __syncthreads();
    for (int o = 128; o > 0; o >>= 1) {
        if (tid < o) red[tid] += red[tid + o];
        __syncthreads();
    }
    const float rstd = rsqrtf(red[0] * (1.f / D) + 1e-6f);

    __half* y = Y + row * D;
#pragma unroll
    for (int i = 0; i < 4; i++) {
        int d0 = tid + i * 256;
        y[d0] = __float2half_rn((v[i] - mean) * rstd * g[d0] + b[d0]);
    }
}

// ====================== embed / out ==========================================
__global__ void __launch_bounds__(256)
patch_k(const float* __restrict__ x, const float* __restrict__ w,
        const float* __restrict__ cb, const float* __restrict__ pe,
        float* __restrict__ T)
{
    const int p  = blockIdx.x;
    const int b  = p >> 8, pp = p & 255;
    const int py = pp >> 4, px = pp & 15;
    const int tid = threadIdx.x;

    __shared__ float patch[48];
    if (tid < 48) {
        int ky = tid / 12, kx = (tid % 12) / 3, cc = tid % 3;
        patch[tid] = x[(((b * 64) + py * 4 + ky) * 64 + (px * 4 + kx)) * 3 + cc];
    }
    __syncthreads();

    float acc[4];
#pragma unroll
    for (int i = 0; i < 4; i++) acc[i] = cb[tid + i * 256];
#pragma unroll
    for (int k = 0; k < 48; k++) {
        float pk = patch[k];
#pragma unroll
        for (int i = 0; i < 4; i++)
            acc[i] = fmaf(pk, w[k * D + tid + i * 256], acc[i]);
    }
    long long base = ((long long)(b * NTOK + 1 + pp)) * D;
#pragma unroll
    for (int i = 0; i < 4; i++) {
        int d0 = tid + i * 256;
        T[base + d0] = acc[i] + pe[(long long)(1 + pp) * D + d0];
    }
}

__global__ void __launch_bounds__(256)
cls_k(const float* __restrict__ cls, const float* __restrict__ pe,
      float* __restrict__ T)
{
    const int b = blockIdx.x, tid = threadIdx.x;
#pragma unroll
    for (int i = 0; i < 4; i++) {
        int d0 = tid + i * 256;
        T[(long long)b * NTOK * D + d0] = cls[d0] + pe[d0];
    }
}

__global__ void __launch_bounds__(256)
out_k(const float* __restrict__ T, float* __restrict__ out)
{
    const int b = blockIdx.x, tid = threadIdx.x;
#pragma unroll
    for (int i = 0; i < 4; i++) {
        int d0 = tid + i * 256;
        out[(long long)b * D + d0] = T[(long long)b * NTOK * D + d0];
    }
}

// ====================== orchestration ========================================
extern "C" void kernel_launch(void* const* d_in, const int* in_sizes, int n_in,
                              void* d_out, int out_size)
{
    const float* x        = (const float*)d_in[0];
    const float* conv_w   = (const float*)d_in[1];
    const float* conv_b   = (const float*)d_in[2];
    const float* cls_tok  = (const float*)d_in[3];
    const float* pos_emb  = (const float*)d_in[4];
    const float* ln1_g    = (const float*)d_in[5];
    const float* ln1_b    = (const float*)d_in[6];
    const float* wq       = (const float*)d_in[7];
    const float* wk       = (const float*)d_in[8];
    const float* wv       = (const float*)d_in[9];
    const float* proj_w   = (const float*)d_in[10];
    const float* proj_b   = (const float*)d_in[11];
    const float* ln2_g    = (const float*)d_in[12];
    const float* ln2_b    = (const float*)d_in[13];
    const float* mlp1_w   = (const float*)d_in[14];
    const float* mlp1_b   = (const float*)d_in[15];
    const float* mlp2_w   = (const float*)d_in[16];
    const float* mlp2_b   = (const float*)d_in[17];
    float* out = (float*)d_out;

    float *t;
    __half *a2, *hbuf, *qb, *kb, *vt, *wbf;
    cudaGetSymbolAddress((void**)&t,    g_t);
    cudaGetSymbolAddress((void**)&a2,   g_a2);
    cudaGetSymbolAddress((void**)&hbuf, g_h);
    cudaGetSymbolAddress((void**)&qb,   g_q);
    cudaGetSymbolAddress((void**)&kb,   g_k);
    cudaGetSymbolAddress((void**)&vt,   g_vt);
    cudaGetSymbolAddress((void**)&wbf,  g_wbf);

    cudaFuncSetAttribute((void*)gemm_mma<2>, cudaFuncAttributeMaxDynamicSharedMemorySize, GEMM_SMEM);
    cudaFuncSetAttribute((void*)gemm_mma<4>, cudaFuncAttributeMaxDynamicSharedMemorySize, GEMM_SMEM);
    cudaFuncSetAttribute((void*)gemm_mma<6>, cudaFuncAttributeMaxDynamicSharedMemorySize, GEMM_SMEM);
    cudaFuncSetAttribute((void*)flash_attn_k, cudaFuncAttributeMaxDynamicSharedMemorySize, FA_SMEM);

    const float qscale = 0.08838834764831845f;   // 128^-0.5
    const int TD = NTOK * D;                      // t row stride per batch cls row

    // ---- weight conversion (batched over layers via gridDim.z) ----
    {
        const long long sDD = (long long)D * D;
        const long long sDF = (long long)D * DF;
        cvtW1_k<<<dim3(D / 32, D / 32, LAYERS), 256>>>(wq, wbf, D, D, qscale, sDD);
        cvtW1_k<<<dim3(D / 32, D / 32, LAYERS), 256>>>(wk, wbf + 1024LL * 1024,
                                                       D, D, 1.f, sDD);
        cvtW1_k<<<dim3(D / 32, D / 32, LAYERS), 256>>>(wv, wbf + 2048LL * 1024,
                                                       D, D, 1.f, sDD);
        cvtW1_k<<<dim3(D / 32, D / 32, LAYERS), 256>>>(proj_w, wbf + W_PROJ,
                                                       D, D, 1.f, sDD);
        cvtW1_k<<<dim3(DF / 32, D / 32, LAYERS), 256>>>(mlp1_w, wbf + W_M1,
                                                        D, DF, 1.f, sDF);
        cvtW1_k<<<dim3(D / 32, DF / 32, LAYERS), 256>>>(mlp2_w, wbf + W_M2,
                                                        DF, D, 1.f, sDF);
    }

    // ---- embed ----
    patch_k<<<BSZ * 256, 256>>>(x, conv_w, conv_b, pos_emb, t);
    cls_k<<<BSZ, 256>>>(cls_tok, pos_emb, t);

    const int Mt = (MTOK + 127) / 128;                 // 129
    const dim3 gQKV(24, Mt);
    const dim3 gD  (8, Mt);
    const dim3 gDF (32, Mt);

    for (int i = 0; i < LAYERS; i++) {
        const __half* wl = wbf + (size_t)i * W_LAYER;
        const float* pb_i = proj_b + (size_t)i * D;
        const float* m1b  = mlp1_b + (size_t)i * DF;
        const float* m2b  = mlp2_b + (size_t)i * D;
        const bool last = (i == LAYERS - 1);

        // LN1 -> fp16 (full; K/V need all tokens)
        ln_half_k<<<MTOK, 256>>>(t, ln1_g + (size_t)i * D, ln1_b + (size_t)i * D,
                                 a2, D);

        // QKV single-term, epilogue routes q/k per-head + v transposed (staged)
        gemm_mma<6><<<gQKV, 256, GEMM_SMEM>>>(a2, wl, nullptr, nullptr,
            nullptr, nullptr, qb, kb, vt, MTOK, D, 0, D);

        // fused attention -> a2; last layer: only cls q-tile
        flash_attn_k<<<last ? dim3(1, BH) : dim3(3, BH), 256, FA_SMEM>>>(qb, kb, vt, a2);

        if (!last) {
            // t += y @ proj_w + proj_b
            gemm_mma<2><<<gD, 256, GEMM_SMEM>>>(a2, wl + W_PROJ, pb_i, t, t,
                nullptr, nullptr, nullptr, nullptr, MTOK, D, D, D);

            // LN2 -> fp16
            ln_half_k<<<MTOK, 256>>>(t, ln2_g + (size_t)i * D,
                                     ln2_b + (size_t)i * D, a2, D);

            // h = gelu(xn @ mlp1_w + b) -> fp16
            gemm_mma<4><<<gDF, 256, GEMM_SMEM>>>(a2, wl + W_M1, m1b, nullptr,
                nullptr, hbuf, nullptr, nullptr, nullptr, MTOK, D, DF, D);

            // t += h @ mlp2_w + b
            gemm_mma<2><<<gD, 256, GEMM_SMEM>>>(hbuf, wl + W_M2, m2b, t, t,
                nullptr, nullptr, nullptr, nullptr, MTOK, DF, D, DF);
        } else {
            // --- last layer: only the 64 cls rows matter downstream ---
            gemm_mma<2><<<dim3(8, 1), 256, GEMM_SMEM>>>(a2, wl + W_PROJ, pb_i,
                t, t, nullptr, nullptr, nullptr, nullptr, BSZ, D, TD, TD);

            ln_half_k<<<BSZ, 256>>>(t, ln2_g + (size_t)i * D,
                                    ln2_b + (size_t)i * D, a2, TD);

            gemm_mma<4><<<dim3(32, 1), 256, GEMM_SMEM>>>(a2, wl + W_M1, m1b,
                nullptr, nullptr, hbuf, nullptr, nullptr, nullptr,
                BSZ, D, DF, D);

            gemm_mma<2><<<dim3(8, 1), 256, GEMM_SMEM>>>(hbuf, wl + W_M2, m2b,
                t, t, nullptr, nullptr, nullptr, nullptr, BSZ, DF, TD, DF);
        }
    }

    out_k<<<BSZ, 256>>>(t, out);
}

// round 17
// speedup vs baseline: 1.0598x; 1.0106x over previous
#include <cuda_runtime.h>
#include <cuda_fp16.h>
#include <cstdint>
#include <math.h>

#define D      1024
#define DF     4096
#define NTOK   257
#define BSZ    64
#define LAYERS 8
#define HEADS  8
#define HD     128
#define MTOK   (BSZ * NTOK)      /* 16448 */
#define BH     (BSZ * HEADS)     /* 512 */
#define KTOT   384               /* vt row width (layout padding) */
#define QK_ROWS 384

// per-layer fp16 weight offsets (elements), all single-term [N, K]
#define W_QKV   0LL
#define W_PROJ  (3072LL * 1024)
#define W_M1    (W_PROJ + 1024LL * 1024)
#define W_M2    (W_M1  + 4096LL * 1024)
#define W_LAYER (W_M2  + 1024LL * 4096)   /* 12582912 */

// ---------------- scratch (device globals; zero-initialized) ----------------
__device__ float g_t  [MTOK * D];
__device__ __align__(16) __half g_a2 [(size_t)MTOK * D];
__device__ __align__(16) __half g_h  [(size_t)MTOK * DF];
__device__ __align__(16) __half g_q  [(size_t)BH * QK_ROWS * HD];
__device__ __align__(16) __half g_k  [(size_t)BH * QK_ROWS * HD];
__device__ __align__(16) __half g_vt [(size_t)BH * HD * KTOT];
__device__ __align__(16) __half g_wbf[(size_t)LAYERS * W_LAYER];

// ============================ PTX helpers ====================================
__device__ __forceinline__ uint32_t smem_u32(const void* p) {
    uint32_t a;
    asm("{ .reg .u64 t; cvta.to.shared.u64 t, %1; cvt.u32.u64 %0, t; }"
        : "=r"(a) : "l"(p));
    return a;
}
__device__ __forceinline__ void cpasync16(uint32_t s, const void* g, uint32_t sz) {
    asm volatile("cp.async.cg.shared.global [%0], [%1], 16, %2;"
                 :: "r"(s), "l"(g), "r"(sz) : "memory");
}
__device__ __forceinline__ void ldsm4(uint32_t& r0, uint32_t& r1,
                                      uint32_t& r2, uint32_t& r3, uint32_t a) {
    asm volatile("ldmatrix.sync.aligned.m8n8.x4.shared.b16 {%0,%1,%2,%3}, [%4];"
                 : "=r"(r0), "=r"(r1), "=r"(r2), "=r"(r3) : "r"(a));
}
__device__ __forceinline__ void mma16816(float* d, const uint32_t* a,
                                         const uint32_t* b) {
    asm volatile("mma.sync.aligned.m16n8k16.row.col.f32.f16.f16.f32 "
                 "{%0,%1,%2,%3}, {%4,%5,%6,%7}, {%8,%9}, {%0,%1,%2,%3};"
                 : "+f"(d[0]), "+f"(d[1]), "+f"(d[2]), "+f"(d[3])
                 : "r"(a[0]), "r"(a[1]), "r"(a[2]), "r"(a[3]),
                   "r"(b[0]), "r"(b[1]));
}

// ====================== fp16 GEMM ============================================
// C[M,N] = A[M,K](fp16) @ B[N,K]^T(fp16)
// A row m at A + m*lda; C row m at +m*ldc; Res row m at +m*ldres.
// EPI: 2 fp32 C = acc + bias + Res
//      4 fp16 Cs = gelu(acc + bias)
//      6 qkv routing (ldc >= 0: column offset ldc added; ldc == -1: q-cls mode)
#define STG_BYTES 32768
#define GEMM_SMEM (3 * STG_BYTES)

template <int EPI>
__global__ void __launch_bounds__(256, 2)
gemm_mma(const __half* __restrict__ A, const __half* __restrict__ Bw,
         const float* __restrict__ bias, const float* __restrict__ Res,
         float* __restrict__ C, __half* __restrict__ Cs,
         __half* __restrict__ Qh, __half* __restrict__ Kh, __half* __restrict__ Vh,
         int M, int K, int ldc, int ldres, int lda)
{
    extern __shared__ char smem[];
    const uint32_t sb = smem_u32(smem);
    const int tid  = threadIdx.x;
    const int wid  = tid >> 5, lane = tid & 31;
    const int wm   = wid & 1, wn = wid >> 1;       // 2 x 4 warp grid
    const int row0 = blockIdx.y * 128, col0 = blockIdx.x * 128;

    const long long rowByA = 2LL * lda;
    const long long rowByB = 2LL * K;

    const int ldrow = tid >> 3, ldch = tid & 7;
    const char* gA = (const char*)A  + (long long)(row0 + ldrow) * rowByA + ldch * 16;
    const char* gB = (const char*)Bw + (long long)(col0 + ldrow) * rowByB + ldch * 16;

    auto load_stage = [&](int kt) {
        const uint32_t st = sb + (kt % 3) * STG_BYTES;
        const long long off = (long long)kt * 128;
#pragma unroll
        for (int i = 0; i < 4; i++) {
            int r = i * 32 + ldrow;
            uint32_t so = (uint32_t)(r * 128 + ((ldch ^ (r & 7)) * 16));
            uint32_t szA = (row0 + r < M) ? 16u : 0u;
            const char* a = szA ? (gA + (long long)i * 32 * rowByA + off)
                                : (const char*)A;
            cpasync16(st + so, a, szA);
            cpasync16(st + 16384 + so, gB + (long long)i * 32 * rowByB + off, 16u);
        }
        asm volatile("cp.async.commit_group;" ::: "memory");
    };

    const int grp = lane >> 3, l8 = lane & 7;
    const int aRowB = wm * 64 + (grp & 1) * 8 + l8;
    const int aCG   = grp >> 1;
    const int bRowB = wn * 32 + (grp >> 1) * 8 + l8;
    const int bCG   = grp & 1;

    float acc[4][4][4];
#pragma unroll
    for (int i = 0; i < 4; i++)
#pragma unroll
        for (int j = 0; j < 4; j++)
#pragma unroll
            for (int r = 0; r < 4; r++) acc[i][j][r] = 0.f;

    const int nkt = K / 64;
    load_stage(0);
    load_stage(1);

    for (int kt = 0; kt < nkt; kt++) {
        asm volatile("cp.async.wait_group 1;" ::: "memory");
        __syncthreads();
        if (kt + 2 < nkt) load_stage(kt + 2);
        else asm volatile("cp.async.commit_group;" ::: "memory");

        const uint32_t sA = sb + (kt % 3) * STG_BYTES;
        const uint32_t sB = sA + 16384;

#pragma unroll
        for (int ks = 0; ks < 4; ks++) {
            uint32_t af[4][4], bf2[2][4];
            const uint32_t aSw = (uint32_t)(((ks * 2 + aCG) ^ l8) * 16);
            const uint32_t bSw = (uint32_t)(((ks * 2 + bCG) ^ l8) * 16);
#pragma unroll
            for (int mi = 0; mi < 4; mi++)
                ldsm4(af[mi][0], af[mi][1], af[mi][2], af[mi][3],
                      sA + (uint32_t)((aRowB + mi * 16) * 128) + aSw);
#pragma unroll
            for (int ni2 = 0; ni2 < 2; ni2++)
                ldsm4(bf2[ni2][0], bf2[ni2][1], bf2[ni2][2], bf2[ni2][3],
                      sB + (uint32_t)((bRowB + ni2 * 16) * 128) + bSw);
#pragma unroll
            for (int mi = 0; mi < 4; mi++)
#pragma unroll
                for (int ni = 0; ni < 4; ni++)
                    mma16816(acc[mi][ni], af[mi], &bf2[ni >> 1][(ni & 1) * 2]);
        }
    }

    const int coff  = (EPI == 6 && ldc > 0) ? ldc : 0;
    const bool qcls = (EPI == 6 && ldc < 0);
    const bool isv  = (EPI == 6) && (col0 + coff >= 2048);
    __half* stile = (__half*)smem;

    // All warps must retire their final ldsm reads of the pipeline stages
    // before any warp overwrites stage 0 with the v staging tile.
    if (isv) __syncthreads();

    // ---- epilogue ----
#pragma unroll
    for (int mi = 0; mi < 4; mi++) {
#pragma unroll
        for (int ni = 0; ni < 4; ni++) {
            float* c = acc[mi][ni];
            int m0 = row0 + wm * 64 + mi * 16 + (lane >> 2);
            int n  = col0 + wn * 32 + ni * 8 + (lane & 3) * 2;
            float b0 = 0.f, b1 = 0.f;
            if (EPI == 2 || EPI == 4) { b0 = bias[n]; b1 = bias[n + 1]; }
#pragma unroll
            for (int half = 0; half < 2; half++) {
                int m = m0 + half * 8;
                if (m >= M && !isv) continue;
                float v0 = c[half * 2 + 0], v1 = c[half * 2 + 1];
                if (EPI == 2) {
                    const float* rp = Res + (size_t)m * ldres + n;
                    v0 += b0 + rp[0]; v1 += b1 + rp[1];
                    *(float2*)(C + (size_t)m * ldc + n) = make_float2(v0, v1);
                }
                if (EPI == 4) {
                    v0 += b0; v1 += b1;
                    v0 = 0.5f * v0 * (1.f + erff(v0 * 0.7071067811865475f));
                    v1 = 0.5f * v1 * (1.f + erff(v1 * 0.7071067811865475f));
                    *(__half2*)(Cs + (size_t)m * ldc + n) = __floats2half2_rn(v0, v1);
                }
                if (EPI == 6) {
                    if (qcls) {
                        // M = BSZ cls rows: b = m, tok = 0; n in [0,1024) = q
                        int h = n >> 7, hd = n & 127;
                        long long bh = (long long)(m * HEADS + h);
                        *(__half2*)(Qh + (bh * QK_ROWS) * HD + hd)
                            = __floats2half2_rn(v0, v1);
                    } else if (!isv) {
                        int n6 = n + coff;
                        int sec = n6 >> 10, h = (n6 & 1023) >> 7, hd = n6 & 127;
                        int b   = m / NTOK, tok = m - b * NTOK;
                        long long bh = (long long)(b * HEADS + h);
                        __half2 hv = __floats2half2_rn(v0, v1);
                        if (sec == 0)
                            *(__half2*)(Qh + (bh * QK_ROWS + tok) * HD + hd) = hv;
                        else
                            *(__half2*)(Kh + (bh * QK_ROWS + tok) * HD + hd) = hv;
                    } else {
                        // stage to smem tile, swizzled: elem (r, c)
                        int r = wm * 64 + mi * 16 + (lane >> 2) + half * 8;
                        int cc = wn * 32 + ni * 8 + (lane & 3) * 2;
                        uint32_t off = (uint32_t)(r * 128
                                     + ((((cc >> 3) ^ (r & 7)) << 3) + (cc & 7)));
                        *(__half2*)(stile + off) = __floats2half2_rn(v0, v1);
                    }
                }
            }
        }
    }

    if (isv) {
        __syncthreads();
        const int h2 = (col0 + coff - 2048) >> 7;   // head (tile spans one head)
#pragma unroll
        for (int nn = 0; nn < 16; nn++) {
            int n = wid * 16 + nn;                  // hd within head
#pragma unroll
            for (int j = 0; j < 4; j++) {
                int mloc = j * 32 + lane;
                int m = row0 + mloc;
                if (m >= M) continue;
                int bb = m / NTOK, tok = m - bb * NTOK;
                uint32_t off = (uint32_t)(mloc * 128
                             + ((((n >> 3) ^ (mloc & 7)) << 3) + (n & 7)));
                Vh[((long long)(bb * HEADS + h2) * HD + n) * KTOT + tok] = stile[off];
            }
        }
    }
}

// ====================== fused flash attention ================================
// grid (mtiles, BH). Keys 0..255 via 2 HMMA K-tiles + key 256 via rank-1
// online-softmax fold (all in-kernel). Q pad rows are zero (harmless).
#define FA_SQ   0
#define FA_SK   32768
#define FA_SV   98304
#define FA_SP   163840
#define FA_WMAX 196608
#define FA_WSUM 198656
#define FA_XK   200704    /* key 256: 128 half */
#define FA_XV   200960    /* value 256: 128 half */
#define FA_SX   201216    /* s_x per row: 128 float */
#define FA_SMEM 201728

__global__ void __launch_bounds__(256, 1)
flash_attn_k(const __half* __restrict__ Q, const __half* __restrict__ Kb,
             const __half* __restrict__ Vt, __half* __restrict__ Y)
{
    extern __shared__ char smem[];
    const uint32_t sb = smem_u32(smem);
    const int tid = threadIdx.x, wid = tid >> 5, lane = tid & 31;
    const int wm = wid & 1, wn = wid >> 1;
    const int mtile = blockIdx.x;
    const int bh = blockIdx.y;
    const int b = bh >> 3, h = bh & 7;

    const int ldrow = tid >> 3, ldch = tid & 7;
    const char* gQ = (const char*)(Q  + ((size_t)bh * QK_ROWS + mtile * 128) * HD);
    const char* gK = (const char*)(Kb + (size_t)bh * QK_ROWS * HD);
    const char* gV = (const char*)(Vt + (size_t)bh * HD * KTOT);

    auto load_tile = [&](uint32_t dst, const char* src, int rowBytes) {
#pragma unroll
        for (int c = 0; c < 2; c++)
#pragma unroll
            for (int i = 0; i < 4; i++) {
                int r = i * 32 + ldrow;
                uint32_t so = dst + (uint32_t)(c * 16384 + r * 128 + ((ldch ^ (r & 7)) * 16));
                cpasync16(so, src + (long long)r * rowBytes + c * 128 + ldch * 16, 16u);
            }
    };

    load_tile(sb + FA_SQ, gQ, 256);
    load_tile(sb + FA_SK, gK, 256);
    load_tile(sb + FA_SV, gV, 2 * KTOT);
    asm volatile("cp.async.commit_group;" ::: "memory");
    load_tile(sb + FA_SK + 32768, gK + 128 * 256, 256);
    load_tile(sb + FA_SV + 32768, gV + 128 * 2, 2 * KTOT);
    asm volatile("cp.async.commit_group;" ::: "memory");

    // key/value 256 -> smem (plain stores; visible after first __syncthreads)
    if (tid < 128)
        ((__half*)(smem + FA_XK))[tid] =
            Kb[((size_t)bh * QK_ROWS + 256) * HD + tid];
    else
        ((__half*)(smem + FA_XV))[tid - 128] =
            Vt[((size_t)bh * HD + (tid - 128)) * KTOT + 256];

    const int grp = lane >> 3, l8 = lane & 7;
    const int aRowB = wm * 64 + (grp & 1) * 8 + l8;
    const int aCG   = grp >> 1;
    const int bRowB = wn * 32 + (grp >> 1) * 8 + l8;
    const int bCG   = grp & 1;
    const int l8r = lane >> 2, qq = lane & 3;

    float* wmax = (float*)(smem + FA_WMAX);   // [4][128]
    float* wsum = (float*)(smem + FA_WSUM);   // [4][128]

    float accO[4][4][4];
#pragma unroll
    for (int i = 0; i < 4; i++)
#pragma unroll
        for (int j = 0; j < 4; j++)
#pragma unroll
            for (int r = 0; r < 4; r++) accO[i][j][r] = 0.f;
    float m_run[8], l_run[8];
#pragma unroll
    for (int i = 0; i < 8; i++) { m_run[i] = -1e30f; l_run[i] = 0.f; }

    auto gemm_tile = [&](uint32_t aBase, uint32_t bBase, float (&acc)[4][4][4]) {
#pragma unroll
        for (int c = 0; c < 2; c++) {
            const uint32_t sA = aBase + c * 16384, sB = bBase + c * 16384;
#pragma unroll
            for (int ks = 0; ks < 4; ks++) {
                uint32_t af[4][4], bf2[2][4];
                const uint32_t aSw = (uint32_t)(((ks * 2 + aCG) ^ l8) * 16);
                const uint32_t bSw = (uint32_t)(((ks * 2 + bCG) ^ l8) * 16);
#pragma unroll
                for (int mi = 0; mi < 4; mi++)
                    ldsm4(af[mi][0], af[mi][1], af[mi][2], af[mi][3],
                          sA + (uint32_t)((aRowB + mi * 16) * 128) + aSw);
#pragma unroll
                for (int ni2 = 0; ni2 < 2; ni2++)
                    ldsm4(bf2[ni2][0], bf2[ni2][1], bf2[ni2][2], bf2[ni2][3],
                          sB + (uint32_t)((bRowB + ni2 * 16) * 128) + bSw);
#pragma unroll
                for (int mi = 0; mi < 4; mi++)
#pragma unroll
                    for (int ni = 0; ni < 4; ni++)
                        mma16816(acc[mi][ni], af[mi], &bf2[ni >> 1][(ni & 1) * 2]);
            }
        }
    };

    for (int kt = 0; kt < 2; kt++) {
        if (kt == 0) asm volatile("cp.async.wait_group 1;" ::: "memory");
        else         asm volatile("cp.async.wait_group 0;" ::: "memory");
        __syncthreads();

        float accS[4][4][4];
#pragma unroll
        for (int i = 0; i < 4; i++)
#pragma unroll
            for (int j = 0; j < 4; j++)
#pragma unroll
                for (int r = 0; r < 4; r++) accS[i][j][r] = 0.f;
        gemm_tile(sb + FA_SQ, sb + FA_SK + kt * 32768, accS);

#pragma unroll
        for (int mi = 0; mi < 4; mi++)
#pragma unroll
            for (int hf = 0; hf < 2; hf++) {
                float r = -1e30f;
#pragma unroll
                for (int ni = 0; ni < 4; ni++) {
                    r = fmaxf(r, accS[mi][ni][hf * 2]);
                    r = fmaxf(r, accS[mi][ni][hf * 2 + 1]);
                }
                r = fmaxf(r, __shfl_xor_sync(0xffffffffu, r, 1));
                r = fmaxf(r, __shfl_xor_sync(0xffffffffu, r, 2));
                if (qq == 0)
                    wmax[wn * 128 + wm * 64 + mi * 16 + hf * 8 + l8r] = r;
            }
        __syncthreads();

        float fscale[8];
#pragma unroll
        for (int mi = 0; mi < 4; mi++)
#pragma unroll
            for (int hf = 0; hf < 2; hf++) {
                int row = wm * 64 + mi * 16 + hf * 8 + l8r;
                float tm = fmaxf(fmaxf(wmax[row], wmax[128 + row]),
                                 fmaxf(wmax[256 + row], wmax[384 + row]));
                int idx = mi * 2 + hf;
                float mnew = fmaxf(m_run[idx], tm);
                float f = __expf(m_run[idx] - mnew);
                m_run[idx] = mnew;
                fscale[idx] = f;
#pragma unroll
                for (int ni = 0; ni < 4; ni++) {
                    accO[mi][ni][hf * 2]     *= f;
                    accO[mi][ni][hf * 2 + 1] *= f;
                }
            }
#pragma unroll
        for (int mi = 0; mi < 4; mi++)
#pragma unroll
            for (int hf = 0; hf < 2; hf++) {
                int idx = mi * 2 + hf;
                int row = wm * 64 + mi * 16 + hf * 8 + l8r;
                float rs = 0.f;
#pragma unroll
                for (int ni = 0; ni < 4; ni++) {
                    int col = wn * 32 + ni * 8 + qq * 2;
                    float p0 = __expf(accS[mi][ni][hf * 2]     - m_run[idx]);
                    float p1 = __expf(accS[mi][ni][hf * 2 + 1] - m_run[idx]);
                    rs += p0 + p1;
                    uint32_t off = (uint32_t)(FA_SP + (col >> 6) * 16384 + row * 128
                                   + ((((col & 63) >> 3) ^ (row & 7)) * 16)
                                   + (col & 7) * 2);
                    *(__half2*)(smem + off) = __floats2half2_rn(p0, p1);
                }
                rs += __shfl_xor_sync(0xffffffffu, rs, 1);
                rs += __shfl_xor_sync(0xffffffffu, rs, 2);
                if (qq == 0) wsum[wn * 128 + row] = rs;
            }
        __syncthreads();
#pragma unroll
        for (int mi = 0; mi < 4; mi++)
#pragma unroll
            for (int hf = 0; hf < 2; hf++) {
                int idx = mi * 2 + hf;
                int row = wm * 64 + mi * 16 + hf * 8 + l8r;
                float rs = wsum[row] + wsum[128 + row] + wsum[256 + row] + wsum[384 + row];
                l_run[idx] = l_run[idx] * fscale[idx] + rs;
            }

        gemm_tile(sb + FA_SP, sb + FA_SV + kt * 32768, accO);
        __syncthreads();
    }

    // ---- extra key 256: s_x = q_row . k256 (2 threads per row) ----
    {
        int row = tid >> 1, hc = tid & 1;
        const __half* xk = (const __half*)(smem + FA_XK);
        float s = 0.f;
#pragma unroll
        for (int cc = 0; cc < 64; cc += 2) {
            int col = hc * 64 + cc;
            uint32_t off = (uint32_t)(FA_SQ + hc * 16384 + row * 128
                         + (((cc >> 3) ^ (row & 7)) << 4) + (cc & 7) * 2);
            float2 qf = __half22float2(*(__half2*)(smem + off));
            float2 kf = __half22float2(*(const __half2*)(xk + col));
            s += qf.x * kf.x + qf.y * kf.y;
        }
        s += __shfl_xor_sync(0xffffffffu, s, 1);
        if (hc == 0) ((float*)(smem + FA_SX))[row] = s;
    }
    __syncthreads();

    // ---- fold key 256 into online softmax + rank-1 O update ----
    {
        const __half* xv = (const __half*)(smem + FA_XV);
        const float* sx = (const float*)(smem + FA_SX);
#pragma unroll
        for (int mi = 0; mi < 4; mi++)
#pragma unroll
            for (int hf = 0; hf < 2; hf++) {
                int idx = mi * 2 + hf;
                int row = wm * 64 + mi * 16 + hf * 8 + l8r;
                float sxr = sx[row];
                float mnew = fmaxf(m_run[idx], sxr);
                float f = __expf(m_run[idx] - mnew);
                float p = __expf(sxr - mnew);
                m_run[idx] = mnew;
                l_run[idx] = l_run[idx] * f + p;
#pragma unroll
                for (int ni = 0; ni < 4; ni++) {
                    int n = wn * 32 + ni * 8 + qq * 2;
                    accO[mi][ni][hf * 2]     = accO[mi][ni][hf * 2] * f
                                             + p * __half2float(xv[n]);
                    accO[mi][ni][hf * 2 + 1] = accO[mi][ni][hf * 2 + 1] * f
                                             + p * __half2float(xv[n + 1]);
                }
            }
    }

    // ---- write out ----
#pragma unroll
    for (int mi = 0; mi < 4; mi++)
#pragma unroll
        for (int hf = 0; hf < 2; hf++) {
            int idx = mi * 2 + hf;
            int row = wm * 64 + mi * 16 + hf * 8 + l8r;
            int tok = mtile * 128 + row;
            if (tok >= NTOK) continue;
            float inv = 1.f / l_run[idx];
#pragma unroll
            for (int ni = 0; ni < 4; ni++) {
                int n = wn * 32 + ni * 8 + qq * 2;
                float o0 = accO[mi][ni][hf * 2] * inv;
                float o1 = accO[mi][ni][hf * 2 + 1] * inv;
                *(__half2*)(Y + ((size_t)(b * NTOK + tok)) * D + h * HD + n)
                    = __floats2half2_rn(o0, o1);
            }
        }
}

// ====================== conversions ==========================================
// W [K,N] fp32 -> Wt fp16 [N, K] single-term, scaled; z batches layers
__global__ void __launch_bounds__(256)
cvtW1_k(const float* __restrict__ W, __half* __restrict__ Wt,
        int K, int N, float scale, long long srcStride)
{
    W  += (long long)blockIdx.z * srcStride;
    Wt += (long long)blockIdx.z * W_LAYER;
    __shared__ float t[32][33];
    const int n0 = blockIdx.x * 32, k0 = blockIdx.y * 32;
    const int tx = threadIdx.x & 31, ty = threadIdx.x >> 5;
#pragma unroll
    for (int i = 0; i < 4; i++)
        t[ty + i * 8][tx] = W[(size_t)(k0 + ty + i * 8) * N + n0 + tx] * scale;
    __syncthreads();
#pragma unroll
    for (int i = 0; i < 4; i++) {
        int n = n0 + ty + i * 8, k = k0 + tx;
        Wt[(size_t)n * K + k] = __float2half_rn(t[tx][ty + i * 8]);
    }
}

// LayerNorm -> fp16, warp-shuffle reduction. X row stride xstride; Y compact.
__global__ void __launch_bounds__(256)
ln_half_k(const float* __restrict__ X, const float* __restrict__ g,
          const float* __restrict__ b, __half* __restrict__ Y, long long xstride)
{
    const long long row = blockIdx.x;
    const float* x = X + row * xstride;
    const int tid = threadIdx.x, lane = tid & 31, wid = tid >> 5;
    float v[4];
    float s = 0.f;
#pragma unroll
    for (int i = 0; i < 4; i++) { v[i] = x[tid + i * 256]; s += v[i]; }
#pragma unroll
    for (int o = 16; o > 0; o >>= 1) s += __shfl_xor_sync(0xffffffffu, s, o);

    __shared__ float red[8];
    if (lane == 0) red[wid] = s;
    __syncthreads();
    float tot = red[0] + red[1] + red[2] + red[3]
              + red[4] + red[5] + red[6] + red[7];
    const float mean = tot * (1.f / D);

    float sq = 0.f;
#pragma unroll
    for (int i = 0; i < 4; i++) { float d0 = v[i] - mean; sq += d0 * d0; }
#pragma unroll
    for (int o = 16; o > 0; o >>= 1) sq += __shfl_xor_sync(0xffffffffu, sq, o);
    __syncthreads();
    if (lane == 0) red[wid] = sq;
    __syncthreads();
    float tot2 = red[0] + red[1] + red[2] + red[3]
               + red[4] + red[5] + red[6] + red[7];
    const float rstd = rsqrtf(tot2 * (1.f / D) + 1e-6f);

    __half* y = Y + row * D;
#pragma unroll
    for (int i = 0; i < 4; i++) {
        int d0 = tid + i * 256;
        y[d0] = __float2half_rn((v[i] - mean) * rstd * g[d0] + b[d0]);
    }
}

// ====================== embed ================================================
__global__ void __launch_bounds__(256)
patch_k(const float* __restrict__ x, const float* __restrict__ w,
        const float* __restrict__ cb, const float* __restrict__ pe,
        float* __restrict__ T)
{
    const int p  = blockIdx.x;
    const int b  = p >> 8, pp = p & 255;
    const int py = pp >> 4, px = pp & 15;
    const int tid = threadIdx.x;

    __shared__ float patch[48];
    if (tid < 48) {
        int ky = tid / 12, kx = (tid % 12) / 3, cc = tid % 3;
        patch[tid] = x[(((b * 64) + py * 4 + ky) * 64 + (px * 4 + kx)) * 3 + cc];
    }
    __syncthreads();

    float acc[4];
#pragma unroll
    for (int i = 0; i < 4; i++) acc[i] = cb[tid + i * 256];
#pragma unroll
    for (int k = 0; k < 48; k++) {
        float pk = patch[k];
#pragma unroll
        for (int i = 0; i < 4; i++)
            acc[i] = fmaf(pk, w[k * D + tid + i * 256], acc[i]);
    }
    long long base = ((long long)(b * NTOK + 1 + pp)) * D;
#pragma unroll
    for (int i = 0; i < 4; i++) {
        int d0 = tid + i * 256;
        T[base + d0] = acc[i] + pe[(long long)(1 + pp) * D + d0];
    }
}

__global__ void __launch_bounds__(256)
cls_k(const float* __restrict__ cls, const float* __restrict__ pe,
      float* __restrict__ T)
{
    const int b = blockIdx.x, tid = threadIdx.x;
#pragma unroll
    for (int i = 0; i < 4; i++) {
        int d0 = tid + i * 256;
        T[(long long)b * NTOK * D + d0] = cls[d0] + pe[d0];
    }
}

// ====================== orchestration ========================================
extern "C" void kernel_launch(void* const* d_in, const int* in_sizes, int n_in,
                              void* d_out, int out_size)
{
    const float* x        = (const float*)d_in[0];
    const float* conv_w   = (const float*)d_in[1];
    const float* conv_b   = (const float*)d_in[2];
    const float* cls_tok  = (const float*)d_in[3];
    const float* pos_emb  = (const float*)d_in[4];
    const float* ln1_g    = (const float*)d_in[5];
    const float* ln1_b    = (const float*)d_in[6];
    const float* wq       = (const float*)d_in[7];
    const float* wk       = (const float*)d_in[8];
    const float* wv       = (const float*)d_in[9];
    const float* proj_w   = (const float*)d_in[10];
    const float* proj_b   = (const float*)d_in[11];
    const float* ln2_g    = (const float*)d_in[12];
    const float* ln2_b    = (const float*)d_in[13];
    const float* mlp1_w   = (const float*)d_in[14];
    const float* mlp1_b   = (const float*)d_in[15];
    const float* mlp2_w   = (const float*)d_in[16];
    const float* mlp2_b   = (const float*)d_in[17];
    float* out = (float*)d_out;

    float *t;
    __half *a2, *hbuf, *qb, *kb, *vt, *wbf;
    cudaGetSymbolAddress((void**)&t,    g_t);
    cudaGetSymbolAddress((void**)&a2,   g_a2);
    cudaGetSymbolAddress((void**)&hbuf, g_h);
    cudaGetSymbolAddress((void**)&qb,   g_q);
    cudaGetSymbolAddress((void**)&kb,   g_k);
    cudaGetSymbolAddress((void**)&vt,   g_vt);
    cudaGetSymbolAddress((void**)&wbf,  g_wbf);

    cudaFuncSetAttribute((void*)gemm_mma<2>, cudaFuncAttributeMaxDynamicSharedMemorySize, GEMM_SMEM);
    cudaFuncSetAttribute((void*)gemm_mma<4>, cudaFuncAttributeMaxDynamicSharedMemorySize, GEMM_SMEM);
    cudaFuncSetAttribute((void*)gemm_mma<6>, cudaFuncAttributeMaxDynamicSharedMemorySize, GEMM_SMEM);
    cudaFuncSetAttribute((void*)flash_attn_k, cudaFuncAttributeMaxDynamicSharedMemorySize, FA_SMEM);

    const float qscale = 0.08838834764831845f;   // 128^-0.5
    const int TD = NTOK * D;                      // t row stride per batch cls row

    // ---- weight conversion (batched over layers via gridDim.z) ----
    {
        const long long sDD = (long long)D * D;
        const long long sDF = (long long)D * DF;
        cvtW1_k<<<dim3(D / 32, D / 32, LAYERS), 256>>>(wq, wbf, D, D, qscale, sDD);
        cvtW1_k<<<dim3(D / 32, D / 32, LAYERS), 256>>>(wk, wbf + 1024LL * 1024,
                                                       D, D, 1.f, sDD);
        cvtW1_k<<<dim3(D / 32, D / 32, LAYERS), 256>>>(wv, wbf + 2048LL * 1024,
                                                       D, D, 1.f, sDD);
        cvtW1_k<<<dim3(D / 32, D / 32, LAYERS), 256>>>(proj_w, wbf + W_PROJ,
                                                       D, D, 1.f, sDD);
        cvtW1_k<<<dim3(DF / 32, D / 32, LAYERS), 256>>>(mlp1_w, wbf + W_M1,
                                                        D, DF, 1.f, sDF);
        cvtW1_k<<<dim3(D / 32, DF / 32, LAYERS), 256>>>(mlp2_w, wbf + W_M2,
                                                        DF, D, 1.f, sDF);
    }

    // ---- embed ----
    patch_k<<<BSZ * 256, 256>>>(x, conv_w, conv_b, pos_emb, t);
    cls_k<<<BSZ, 256>>>(cls_tok, pos_emb, t);

    const int Mt = (MTOK + 127) / 128;                 // 129
    const dim3 gQKV(24, Mt);
    const dim3 gKV (16, Mt);
    const dim3 gD  (8, Mt);
    const dim3 gDF (32, Mt);

    for (int i = 0; i < LAYERS; i++) {
        const __half* wl = wbf + (size_t)i * W_LAYER;
        const float* pb_i = proj_b + (size_t)i * D;
        const float* m1b  = mlp1_b + (size_t)i * DF;
        const float* m2b  = mlp2_b + (size_t)i * D;
        const bool last = (i == LAYERS - 1);

        // LN1 -> fp16 (full; K/V need all tokens)
        ln_half_k<<<MTOK, 256>>>(t, ln1_g + (size_t)i * D, ln1_b + (size_t)i * D,
                                 a2, D);

        if (!last) {
            // full QKV: routes q/k per-head + v transposed (staged)
            gemm_mma<6><<<gQKV, 256, GEMM_SMEM>>>(a2, wl, nullptr, nullptr,
                nullptr, nullptr, qb, kb, vt, MTOK, D, 0, 0, D);
        } else {
            // K/V only (column offset 1024 into qkv space)
            gemm_mma<6><<<gKV, 256, GEMM_SMEM>>>(a2, wl + 1024LL * 1024,
                nullptr, nullptr, nullptr, nullptr, qb, kb, vt,
                MTOK, D, 1024, 0, D);
            // q for the 64 cls rows only (qcls routing, strided A)
            gemm_mma<6><<<dim3(8, 1), 256, GEMM_SMEM>>>(a2, wl,
                nullptr, nullptr, nullptr, nullptr, qb, kb, vt,
                BSZ, D, -1, 0, TD);
        }

        // fused attention -> a2; last layer: only cls q-tile
        flash_attn_k<<<last ? dim3(1, BH) : dim3(3, BH), 256, FA_SMEM>>>(qb, kb, vt, a2);

        if (!last) {
            // t += y @ proj_w + proj_b
            gemm_mma<2><<<gD, 256, GEMM_SMEM>>>(a2, wl + W_PROJ, pb_i, t, t,
                nullptr, nullptr, nullptr, nullptr, MTOK, D, D, D, D);

            // LN2 -> fp16
            ln_half_k<<<MTOK, 256>>>(t, ln2_g + (size_t)i * D,
                                     ln2_b + (size_t)i * D, a2, D);

            // h = gelu(xn @ mlp1_w + b) -> fp16
            gemm_mma<4><<<gDF, 256, GEMM_SMEM>>>(a2, wl + W_M1, m1b, nullptr,
                nullptr, hbuf, nullptr, nullptr, nullptr, MTOK, D, DF, 0, D);

            // t += h @ mlp2_w + b
            gemm_mma<2><<<gD, 256, GEMM_SMEM>>>(hbuf, wl + W_M2, m2b, t, t,
                nullptr, nullptr, nullptr, nullptr, MTOK, DF, D, D, DF);
        } else {
            // --- last layer: only the 64 cls rows matter downstream ---
            gemm_mma<2><<<dim3(8, 1), 256, GEMM_SMEM>>>(a2, wl + W_PROJ, pb_i,
                t, t, nullptr, nullptr, nullptr, nullptr, BSZ, D, TD, TD, TD);

            ln_half_k<<<BSZ, 256>>>(t, ln2_g + (size_t)i * D,
                                    ln2_b + (size_t)i * D, a2, TD);

            gemm_mma<4><<<dim3(32, 1), 256, GEMM_SMEM>>>(a2, wl + W_M1, m1b,
                nullptr, nullptr, hbuf, nullptr, nullptr, nullptr,
                BSZ, D, DF, 0, D);

            // final: out = t_cls + h @ mlp2_w + b  (writes d_out directly)
            gemm_mma<2><<<dim3(8, 1), 256, GEMM_SMEM>>>(hbuf, wl + W_M2, m2b,
                t, out, nullptr, nullptr, nullptr, nullptr, BSZ, DF, D, TD, DF);
        }
    }
}